// round 1
// baseline (speedup 1.0000x reference)
#include <cuda_runtime.h>
#include <math.h>

// Problem constants
#define BB   2
#define LL   2048
#define DD   2048
#define NHQ  32
#define NHKV 8
#define HD   64
#define GRP  4           // NHQ / NHKV

// Scratch (allocation-free rule: __device__ globals)
__device__ float g_q[BB * LL * NHQ * HD];      // [B*L, 2048]
__device__ float g_k[BB * LL * NHKV * HD];     // [B*L, 512]
__device__ float g_v[BB * LL * NHKV * HD];     // [B*L, 512]
__device__ float g_ctx[BB * LL * NHQ * HD];    // [B*L, 2048]

// ---------------------------------------------------------------------------
// SGEMM with bias: C[M,N] = A[M,K] @ B[K,N] + bias[N]
// 128x128 block tile, BK=8, 256 threads, 8x8 per-thread microtile.
// All dims are multiples of the tiles (M=4096, N in {512,2048}, K=2048).
// ---------------------------------------------------------------------------
__global__ __launch_bounds__(256) void sgemm_bias(
    const float* __restrict__ A, const float* __restrict__ B,
    const float* __restrict__ bias, float* __restrict__ C,
    int M, int N, int K)
{
    __shared__ float As[8][128];   // [k][m]
    __shared__ float Bs[8][128];   // [k][n]

    const int tid = threadIdx.x;
    const int tx = tid & 15;       // n-dimension
    const int ty = tid >> 4;       // m-dimension
    const int bm = blockIdx.y * 128;
    const int bn = blockIdx.x * 128;

    // A load: each thread loads one float4 (row a_r, k-offset a_k)
    const int a_r = tid >> 1;
    const int a_k = (tid & 1) * 4;
    // B load: each thread loads one float4 (k-row b_k, col b_c)
    const int b_k = tid >> 5;
    const int b_c = (tid & 31) * 4;

    const float* Aptr = A + (long)(bm + a_r) * K + a_k;
    const float* Bptr = B + (long)b_k * N + bn + b_c;

    float acc[8][8];
#pragma unroll
    for (int i = 0; i < 8; i++)
#pragma unroll
        for (int j = 0; j < 8; j++) acc[i][j] = 0.0f;

    for (int k0 = 0; k0 < K; k0 += 8) {
        float4 av = *(const float4*)(Aptr + k0);
        As[a_k + 0][a_r] = av.x;
        As[a_k + 1][a_r] = av.y;
        As[a_k + 2][a_r] = av.z;
        As[a_k + 3][a_r] = av.w;
        *(float4*)&Bs[b_k][b_c] = *(const float4*)(Bptr + (long)k0 * N);
        __syncthreads();

#pragma unroll
        for (int kk = 0; kk < 8; ++kk) {
            float a[8], b[8];
            *(float4*)&a[0] = *(float4*)&As[kk][ty * 4];
            *(float4*)&a[4] = *(float4*)&As[kk][64 + ty * 4];
            *(float4*)&b[0] = *(float4*)&Bs[kk][tx * 4];
            *(float4*)&b[4] = *(float4*)&Bs[kk][64 + tx * 4];
#pragma unroll
            for (int i = 0; i < 8; i++)
#pragma unroll
                for (int j = 0; j < 8; j++)
                    acc[i][j] += a[i] * b[j];
        }
        __syncthreads();
    }

#pragma unroll
    for (int i = 0; i < 8; i++) {
        const int ml = (i < 4) ? (ty * 4 + i) : (64 + ty * 4 + (i - 4));
        const long rowoff = (long)(bm + ml) * N + bn;
#pragma unroll
        for (int jh = 0; jh < 2; jh++) {
            const int nl = jh ? (64 + tx * 4) : (tx * 4);
            float4 o;
            o.x = acc[i][jh * 4 + 0] + bias[bn + nl + 0];
            o.y = acc[i][jh * 4 + 1] + bias[bn + nl + 1];
            o.z = acc[i][jh * 4 + 2] + bias[bn + nl + 2];
            o.w = acc[i][jh * 4 + 3] + bias[bn + nl + 3];
            *(float4*)&C[rowoff + nl] = o;
        }
    }
}

// ---------------------------------------------------------------------------
// Flash-style GQA attention, fp32.
// Block = (q_tile 64 rows, head h, batch b). 256 threads, 4x4 microtile.
// Online softmax over 32 K-tiles of 64.
// smem (dynamic): Qs[d][q], Ks[d][k], Vs[k][d], Ps[k][q], pad 68.
// ---------------------------------------------------------------------------
#define PAD 68

__global__ __launch_bounds__(256) void attn_kernel(
    const float* __restrict__ q, const float* __restrict__ k,
    const float* __restrict__ v, float* __restrict__ ctx)
{
    extern __shared__ float smem[];
    float* Qs = smem;                // [64][PAD]  (d-major: Qs[d][qrow])
    float* Ks = Qs + 64 * PAD;       // [64][PAD]  (d-major: Ks[d][kcol])
    float* Vs = Ks + 64 * PAD;       // [64][PAD]  (k-major: Vs[krow][d])
    float* Ps = Vs + 64 * PAD;       // [64][PAD]  (k-major: Ps[kcol][qrow])

    const int tid = threadIdx.x;
    const int tx = tid & 15;         // owns k-cols / dims tx*4..+3
    const int ty = tid >> 4;         // owns q-rows ty*4..+3
    const int qt = blockIdx.x;
    const int h  = blockIdx.y;       // flat q head; kv head = h / GRP
    const int b  = blockIdx.z;
    const int hk = h >> 2;
    const int qbase = qt * 64;

    // Load + scale Q tile, transposed into Qs[d][q]
    {
        const int r  = tid >> 2;
        const int d0 = (tid & 3) * 16;
        const float* src = q + ((long)(b * LL + qbase + r)) * (NHQ * HD) + h * HD + d0;
#pragma unroll
        for (int c = 0; c < 4; c++) {
            float4 vq = *(const float4*)(src + c * 4);
            Qs[(d0 + c * 4 + 0) * PAD + r] = vq.x * 0.125f;
            Qs[(d0 + c * 4 + 1) * PAD + r] = vq.y * 0.125f;
            Qs[(d0 + c * 4 + 2) * PAD + r] = vq.z * 0.125f;
            Qs[(d0 + c * 4 + 3) * PAD + r] = vq.w * 0.125f;
        }
    }

    float o[4][4];
    float m[4], l[4];
#pragma unroll
    for (int i = 0; i < 4; i++) {
        m[i] = -1e30f; l[i] = 0.0f;
#pragma unroll
        for (int j = 0; j < 4; j++) o[i][j] = 0.0f;
    }

    for (int kt = 0; kt < LL / 64; ++kt) {
        __syncthreads();   // prior P@V + K/V reads complete
        // Load K (transposed -> Ks[d][kcol]) and V (direct -> Vs[krow][d])
        {
            const int r  = tid >> 2;
            const int d0 = (tid & 3) * 16;
            const long rowbase = (long)(b * LL + kt * 64 + r) * (NHKV * HD) + hk * HD + d0;
            const float* ksrc = k + rowbase;
            const float* vsrc = v + rowbase;
#pragma unroll
            for (int c = 0; c < 4; c++) {
                float4 vk = *(const float4*)(ksrc + c * 4);
                Ks[(d0 + c * 4 + 0) * PAD + r] = vk.x;
                Ks[(d0 + c * 4 + 1) * PAD + r] = vk.y;
                Ks[(d0 + c * 4 + 2) * PAD + r] = vk.z;
                Ks[(d0 + c * 4 + 3) * PAD + r] = vk.w;
                *(float4*)&Vs[r * PAD + d0 + c * 4] = *(const float4*)(vsrc + c * 4);
            }
        }
        __syncthreads();

        // S = Q^T K  (64x64), thread owns s[4][4]
        float s[4][4];
#pragma unroll
        for (int i = 0; i < 4; i++)
#pragma unroll
            for (int j = 0; j < 4; j++) s[i][j] = 0.0f;

#pragma unroll 8
        for (int d = 0; d < 64; ++d) {
            float a[4], bb[4];
            *(float4*)&a[0]  = *(float4*)&Qs[d * PAD + ty * 4];
            *(float4*)&bb[0] = *(float4*)&Ks[d * PAD + tx * 4];
#pragma unroll
            for (int i = 0; i < 4; i++)
#pragma unroll
                for (int j = 0; j < 4; j++)
                    s[i][j] += a[i] * bb[j];
        }

        // Online softmax (row groups = 16 threads sharing ty, lanes consecutive)
#pragma unroll
        for (int i = 0; i < 4; i++) {
            float tm = s[i][0];
            tm = fmaxf(tm, s[i][1]); tm = fmaxf(tm, s[i][2]); tm = fmaxf(tm, s[i][3]);
#pragma unroll
            for (int msk = 1; msk < 16; msk <<= 1)
                tm = fmaxf(tm, __shfl_xor_sync(0xffffffffu, tm, msk));
            const float mn = fmaxf(m[i], tm);
            const float alpha = __expf(m[i] - mn);
            m[i] = mn;
            float rs = 0.0f;
#pragma unroll
            for (int j = 0; j < 4; j++) {
                s[i][j] = __expf(s[i][j] - mn);
                rs += s[i][j];
            }
#pragma unroll
            for (int msk = 1; msk < 16; msk <<= 1)
                rs += __shfl_xor_sync(0xffffffffu, rs, msk);
            l[i] = l[i] * alpha + rs;
#pragma unroll
            for (int j = 0; j < 4; j++) o[i][j] *= alpha;
        }

        // Write P transposed: Ps[kcol][qrow]
#pragma unroll
        for (int i = 0; i < 4; i++)
#pragma unroll
            for (int j = 0; j < 4; j++)
                Ps[(tx * 4 + j) * PAD + ty * 4 + i] = s[i][j];
        __syncthreads();

        // O += P @ V
#pragma unroll 8
        for (int kk = 0; kk < 64; ++kk) {
            float a[4], bb[4];
            *(float4*)&a[0]  = *(float4*)&Ps[kk * PAD + ty * 4];
            *(float4*)&bb[0] = *(float4*)&Vs[kk * PAD + tx * 4];
#pragma unroll
            for (int i = 0; i < 4; i++)
#pragma unroll
                for (int j = 0; j < 4; j++)
                    o[i][j] += a[i] * bb[j];
        }
    }

    // Normalize and write ctx
#pragma unroll
    for (int i = 0; i < 4; i++) {
        const float inv = 1.0f / l[i];
        const int lq = qbase + ty * 4 + i;
        float4 ov;
        ov.x = o[i][0] * inv; ov.y = o[i][1] * inv;
        ov.z = o[i][2] * inv; ov.w = o[i][3] * inv;
        *(float4*)&ctx[((long)(b * LL + lq)) * (NHQ * HD) + h * HD + tx * 4] = ov;
    }
}

// ---------------------------------------------------------------------------
extern "C" void kernel_launch(void* const* d_in, const int* in_sizes, int n_in,
                              void* d_out, int out_size)
{
    const float* x  = (const float*)d_in[0];
    const float* Wq = (const float*)d_in[1];
    const float* bq = (const float*)d_in[2];
    const float* Wk = (const float*)d_in[3];
    const float* bk = (const float*)d_in[4];
    const float* Wv = (const float*)d_in[5];
    const float* bv = (const float*)d_in[6];
    const float* Wo = (const float*)d_in[7];
    const float* bo = (const float*)d_in[8];
    float* out = (float*)d_out;

    float *gq, *gk, *gv, *gctx;
    cudaGetSymbolAddress((void**)&gq, g_q);
    cudaGetSymbolAddress((void**)&gk, g_k);
    cudaGetSymbolAddress((void**)&gv, g_v);
    cudaGetSymbolAddress((void**)&gctx, g_ctx);

    const int M = BB * LL;   // 4096

    // QKV projections
    {
        dim3 gq_grid(NHQ * HD / 128, M / 128);     // (16, 32)
        sgemm_bias<<<gq_grid, 256>>>(x, Wq, bq, gq, M, NHQ * HD, DD);
        dim3 gk_grid(NHKV * HD / 128, M / 128);    // (4, 32)
        sgemm_bias<<<gk_grid, 256>>>(x, Wk, bk, gk, M, NHKV * HD, DD);
        sgemm_bias<<<gk_grid, 256>>>(x, Wv, bv, gv, M, NHKV * HD, DD);
    }

    // Attention
    {
        const int smem_bytes = 4 * 64 * PAD * (int)sizeof(float);  // 69632
        cudaFuncSetAttribute(attn_kernel,
                             cudaFuncAttributeMaxDynamicSharedMemorySize,
                             smem_bytes);
        dim3 grid(LL / 64, NHQ, BB);   // (32, 32, 2)
        attn_kernel<<<grid, 256, smem_bytes>>>(gq, gk, gv, gctx);
    }

    // Output projection
    {
        dim3 go_grid(DD / 128, M / 128);           // (16, 32)
        sgemm_bias<<<go_grid, 256>>>(gctx, Wo, bo, out, M, DD, DD);
    }
}

// round 2
// speedup vs baseline: 2.0141x; 2.0141x over previous
#include <cuda_runtime.h>
#include <cstdint>
#include <math.h>

// Problem constants
#define BB   2
#define LL   2048
#define DD   2048
#define NHQ  32
#define NHKV 8
#define HD   64
#define GRP  4

// Scratch (allocation-free rule: __device__ globals)
__device__ float g_q[BB * LL * NHQ * HD];
__device__ float g_k[BB * LL * NHKV * HD];
__device__ float g_v[BB * LL * NHKV * HD];
__device__ float g_ctx[BB * LL * NHQ * HD];

// ---------------------------------------------------------------------------
// helpers
// ---------------------------------------------------------------------------
__device__ __forceinline__ uint32_t f2tf32(float f) {
    uint32_t u;
    asm("cvt.rna.tf32.f32 %0, %1;" : "=r"(u) : "f"(f));
    return u;
}

__device__ __forceinline__ void mma_tf32(float* d, const uint32_t* a, const uint32_t* b) {
    asm volatile(
        "mma.sync.aligned.m16n8k8.row.col.f32.tf32.tf32.f32 "
        "{%0,%1,%2,%3}, {%4,%5,%6,%7}, {%8,%9}, {%0,%1,%2,%3};"
        : "+f"(d[0]), "+f"(d[1]), "+f"(d[2]), "+f"(d[3])
        : "r"(a[0]), "r"(a[1]), "r"(a[2]), "r"(a[3]), "r"(b[0]), "r"(b[1]));
}

__device__ __forceinline__ void cpasync16(uint32_t saddr, const void* g) {
    asm volatile("cp.async.cg.shared.global [%0], [%1], 16;\n" :: "r"(saddr), "l"(g) : "memory");
}
__device__ __forceinline__ void cp_commit() {
    asm volatile("cp.async.commit_group;\n" ::: "memory");
}
template <int N>
__device__ __forceinline__ void cp_wait() {
    asm volatile("cp.async.wait_group %0;\n" :: "n"(N) : "memory");
}

// ---------------------------------------------------------------------------
// tf32 tensor-core GEMM: C[M,N] = A[M,K] @ B[K,N] + bias
// 128x128x16 block, 256 threads (8 warps, 2x4), warp tile 64x32.
// ---------------------------------------------------------------------------
#define AS_STR 20
#define BS_STR 136

__global__ __launch_bounds__(256) void sgemm_tf32(
    const float* __restrict__ A, const float* __restrict__ B,
    const float* __restrict__ bias, float* __restrict__ C,
    int M, int N, int K)
{
    __shared__ float As[128 * AS_STR];   // [m][k] tf32 bits, stride 20
    __shared__ float Bs[16 * BS_STR];    // [k][n] tf32 bits, stride 136

    const int tid = threadIdx.x;
    const int warp = tid >> 5;
    const int lane = tid & 31;
    const int gid = lane >> 2;   // group id (row within fragment)
    const int tig = lane & 3;    // thread in group
    const int warp_m = warp >> 2;  // 0..1
    const int warp_n = warp & 3;   // 0..3
    const int bm = blockIdx.y * 128;
    const int bn = blockIdx.x * 128;

    // A gmem: thread covers (a_row, a_kc..+3) and (a_row+64, ...)
    const int a_row = tid >> 2;
    const int a_kc = (tid & 3) * 4;
    const float* Ap = A + (long)(bm + a_row) * K + a_kc;
    // B gmem: thread covers (b_k, b_nc..+3) and (b_k+8, ...)
    const int b_k = tid >> 5;
    const int b_nc = (tid & 31) * 4;
    const float* Bp = B + (long)b_k * N + bn + b_nc;

    float acc[4][4][4];
#pragma unroll
    for (int i = 0; i < 4; i++)
#pragma unroll
        for (int j = 0; j < 4; j++)
#pragma unroll
            for (int r = 0; r < 4; r++) acc[i][j][r] = 0.0f;

    float4 pa0 = *(const float4*)(Ap);
    float4 pa1 = *(const float4*)(Ap + (long)64 * K);
    float4 pb0 = *(const float4*)(Bp);
    float4 pb1 = *(const float4*)(Bp + (long)8 * N);

#pragma unroll 1
    for (int k0 = 0; k0 < K; k0 += 16) {
        // store (with tf32 rounding) to smem
        {
            float4 t;
            t.x = __uint_as_float(f2tf32(pa0.x)); t.y = __uint_as_float(f2tf32(pa0.y));
            t.z = __uint_as_float(f2tf32(pa0.z)); t.w = __uint_as_float(f2tf32(pa0.w));
            *(float4*)&As[a_row * AS_STR + a_kc] = t;
            t.x = __uint_as_float(f2tf32(pa1.x)); t.y = __uint_as_float(f2tf32(pa1.y));
            t.z = __uint_as_float(f2tf32(pa1.z)); t.w = __uint_as_float(f2tf32(pa1.w));
            *(float4*)&As[(64 + a_row) * AS_STR + a_kc] = t;
            t.x = __uint_as_float(f2tf32(pb0.x)); t.y = __uint_as_float(f2tf32(pb0.y));
            t.z = __uint_as_float(f2tf32(pb0.z)); t.w = __uint_as_float(f2tf32(pb0.w));
            *(float4*)&Bs[b_k * BS_STR + b_nc] = t;
            t.x = __uint_as_float(f2tf32(pb1.x)); t.y = __uint_as_float(f2tf32(pb1.y));
            t.z = __uint_as_float(f2tf32(pb1.z)); t.w = __uint_as_float(f2tf32(pb1.w));
            *(float4*)&Bs[(8 + b_k) * BS_STR + b_nc] = t;
        }
        __syncthreads();

        if (k0 + 16 < K) {
            pa0 = *(const float4*)(Ap + k0 + 16);
            pa1 = *(const float4*)(Ap + (long)64 * K + k0 + 16);
            pb0 = *(const float4*)(Bp + (long)(k0 + 16) * N);
            pb1 = *(const float4*)(Bp + (long)(k0 + 24) * N);
        }

#pragma unroll
        for (int ks = 0; ks < 2; ks++) {
            uint32_t af[4][4], bf[4][2];
#pragma unroll
            for (int mt = 0; mt < 4; mt++) {
                const int base = (warp_m * 64 + mt * 16 + gid) * AS_STR + ks * 8 + tig;
                af[mt][0] = __float_as_uint(As[base]);
                af[mt][1] = __float_as_uint(As[base + 8 * AS_STR]);
                af[mt][2] = __float_as_uint(As[base + 4]);
                af[mt][3] = __float_as_uint(As[base + 8 * AS_STR + 4]);
            }
#pragma unroll
            for (int nt = 0; nt < 4; nt++) {
                const int col = warp_n * 32 + nt * 8 + gid;
                bf[nt][0] = __float_as_uint(Bs[(ks * 8 + tig) * BS_STR + col]);
                bf[nt][1] = __float_as_uint(Bs[(ks * 8 + tig + 4) * BS_STR + col]);
            }
#pragma unroll
            for (int mt = 0; mt < 4; mt++)
#pragma unroll
                for (int nt = 0; nt < 4; nt++)
                    mma_tf32(acc[mt][nt], af[mt], bf[nt]);
        }
        __syncthreads();
    }

    // epilogue: bias + store (float2 per row-half)
#pragma unroll
    for (int mt = 0; mt < 4; mt++) {
        const int r0 = bm + warp_m * 64 + mt * 16 + gid;
#pragma unroll
        for (int nt = 0; nt < 4; nt++) {
            const int c0 = bn + warp_n * 32 + nt * 8 + 2 * tig;
            const float bx = bias[c0], by = bias[c0 + 1];
            float2 o0 = make_float2(acc[mt][nt][0] + bx, acc[mt][nt][1] + by);
            float2 o1 = make_float2(acc[mt][nt][2] + bx, acc[mt][nt][3] + by);
            *(float2*)&C[(long)r0 * N + c0] = o0;
            *(float2*)&C[(long)(r0 + 8) * N + c0] = o1;
        }
    }
}

// ---------------------------------------------------------------------------
// tf32 tensor-core flash attention.
// Block: 64 q rows x head x batch. 128 threads (4 warps), warp = 16 q rows.
// K/V double-buffered via cp.async. P round-trips through smem.
// smem strides: Ks 68, Vs 72, Ps 68 (frag loads conflict-free).
// ---------------------------------------------------------------------------
#define KS_STR 68
#define VS_STR 72
#define PS_STR 68
#define KS_FLOATS (64 * KS_STR)   // 4352
#define VS_FLOATS (64 * VS_STR)   // 4608
#define NKT (LL / 64)             // 32

__global__ __launch_bounds__(128) void attn_tf32(
    const float* __restrict__ q, const float* __restrict__ k,
    const float* __restrict__ v, float* __restrict__ ctx)
{
    extern __shared__ float sm[];
    float* KsB = sm;                       // 2 x [64][68]
    float* VsB = sm + 2 * KS_FLOATS;       // 2 x [64][72]
    float* Ps  = sm + 2 * KS_FLOATS + 2 * VS_FLOATS;  // [64][68]

    const int tid = threadIdx.x;
    const int warp = tid >> 5;
    const int lane = tid & 31;
    const int gid = lane >> 2;
    const int tig = lane & 3;
    const int qt = blockIdx.x;
    const int h  = blockIdx.y;
    const int b  = blockIdx.z;
    const int hk = h >> 2;
    const int qbase = qt * 64;

    const uint32_t ks_s = (uint32_t)__cvta_generic_to_shared(KsB);
    const uint32_t vs_s = (uint32_t)__cvta_generic_to_shared(VsB);

    // ---- Q fragments, register resident for the whole block ----
    uint32_t qf[8][4];
    {
        const float* qp = q + (long)(b * LL + qbase + warp * 16 + gid) * (NHQ * HD) + h * HD;
        const float* qp8 = qp + (long)8 * (NHQ * HD);
#pragma unroll
        for (int ks = 0; ks < 8; ks++) {
            const int c = ks * 8 + tig;
            qf[ks][0] = f2tf32(qp[c] * 0.125f);
            qf[ks][1] = f2tf32(qp8[c] * 0.125f);
            qf[ks][2] = f2tf32(qp[c + 4] * 0.125f);
            qf[ks][3] = f2tf32(qp8[c + 4] * 0.125f);
        }
    }

    float o[8][4];
    float m[2], l[2];
#pragma unroll
    for (int nt = 0; nt < 8; nt++)
#pragma unroll
        for (int r = 0; r < 4; r++) o[nt][r] = 0.0f;
    m[0] = m[1] = -1e30f;
    l[0] = l[1] = 0.0f;

    const long kvrow_stride = (long)(NHKV * HD);
    const float* kbase = k + (long)(b * LL) * kvrow_stride + hk * HD;
    const float* vbase = v + (long)(b * LL) * kvrow_stride + hk * HD;

    // issue tile 0
    {
        const int buf = 0;
#pragma unroll
        for (int j = 0; j < 8; j++) {
            const int id = tid + 128 * j;
            const int row = id >> 4;
            const int c4 = (id & 15) * 4;
            const long goff = (long)row * kvrow_stride + c4;
            cpasync16(ks_s + (buf * KS_FLOATS + row * KS_STR + c4) * 4, kbase + goff);
            cpasync16(vs_s + (buf * VS_FLOATS + row * VS_STR + c4) * 4, vbase + goff);
        }
        cp_commit();
    }

#pragma unroll 1
    for (int kt = 0; kt < NKT; kt++) {
        const int buf = kt & 1;
        if (kt + 1 < NKT) {
            const int nbuf = buf ^ 1;
            const long tbase = (long)((kt + 1) * 64);
#pragma unroll
            for (int j = 0; j < 8; j++) {
                const int id = tid + 128 * j;
                const int row = id >> 4;
                const int c4 = (id & 15) * 4;
                const long goff = (tbase + row) * kvrow_stride + c4;
                cpasync16(ks_s + (nbuf * KS_FLOATS + row * KS_STR + c4) * 4, kbase + goff);
                cpasync16(vs_s + (nbuf * VS_FLOATS + row * VS_STR + c4) * 4, vbase + goff);
            }
            cp_commit();
            cp_wait<1>();
        } else {
            cp_wait<0>();
        }
        __syncthreads();

        const float* Ks = KsB + buf * KS_FLOATS;
        const float* Vs = VsB + buf * VS_FLOATS;

        // ---- S = Q @ K^T ----
        float sacc[8][4];
#pragma unroll
        for (int nt = 0; nt < 8; nt++)
#pragma unroll
            for (int r = 0; r < 4; r++) sacc[nt][r] = 0.0f;

#pragma unroll
        for (int ks = 0; ks < 8; ks++) {
            uint32_t bf[8][2];
#pragma unroll
            for (int nt = 0; nt < 8; nt++) {
                const int rowb = (nt * 8 + gid) * KS_STR + ks * 8 + tig;
                bf[nt][0] = f2tf32(Ks[rowb]);
                bf[nt][1] = f2tf32(Ks[rowb + 4]);
            }
#pragma unroll
            for (int nt = 0; nt < 8; nt++)
                mma_tf32(sacc[nt], qf[ks], bf[nt]);
        }

        // ---- online softmax (rows gid, gid+8 of this warp's 16) ----
#pragma unroll
        for (int i = 0; i < 2; i++) {
            const int r0 = 2 * i;      // regs r0, r0+1 hold this row's values
            float tm = -1e30f;
#pragma unroll
            for (int nt = 0; nt < 8; nt++)
                tm = fmaxf(tm, fmaxf(sacc[nt][r0], sacc[nt][r0 + 1]));
            tm = fmaxf(tm, __shfl_xor_sync(0xffffffffu, tm, 1));
            tm = fmaxf(tm, __shfl_xor_sync(0xffffffffu, tm, 2));
            const float mn = fmaxf(m[i], tm);
            const float alpha = __expf(m[i] - mn);
            m[i] = mn;
            float rs = 0.0f;
            const int prow = (warp * 16 + gid + 8 * i) * PS_STR + 2 * tig;
#pragma unroll
            for (int nt = 0; nt < 8; nt++) {
                float p0 = __expf(sacc[nt][r0] - mn);
                float p1 = __expf(sacc[nt][r0 + 1] - mn);
                rs += p0 + p1;
                Ps[prow + nt * 8]     = __uint_as_float(f2tf32(p0));
                Ps[prow + nt * 8 + 1] = __uint_as_float(f2tf32(p1));
            }
            rs += __shfl_xor_sync(0xffffffffu, rs, 1);
            rs += __shfl_xor_sync(0xffffffffu, rs, 2);
            l[i] = l[i] * alpha + rs;
#pragma unroll
            for (int nt = 0; nt < 8; nt++) {
                o[nt][r0]     *= alpha;
                o[nt][r0 + 1] *= alpha;
            }
        }
        __syncwarp();

        // ---- O += P @ V ----
#pragma unroll
        for (int ks = 0; ks < 8; ks++) {
            uint32_t pf[4], vf[8][2];
            const int pbase = (warp * 16 + gid) * PS_STR + ks * 8 + tig;
            pf[0] = __float_as_uint(Ps[pbase]);
            pf[1] = __float_as_uint(Ps[pbase + 8 * PS_STR]);
            pf[2] = __float_as_uint(Ps[pbase + 4]);
            pf[3] = __float_as_uint(Ps[pbase + 8 * PS_STR + 4]);
#pragma unroll
            for (int nt = 0; nt < 8; nt++) {
                const int rb = (ks * 8 + tig) * VS_STR + nt * 8 + gid;
                vf[nt][0] = f2tf32(Vs[rb]);
                vf[nt][1] = f2tf32(Vs[rb + 4 * VS_STR]);
            }
#pragma unroll
            for (int nt = 0; nt < 8; nt++)
                mma_tf32(o[nt], pf, vf[nt]);
        }
        __syncthreads();
    }

    // ---- normalize + store ----
    {
        const float inv0 = 1.0f / l[0];
        const float inv1 = 1.0f / l[1];
        float* cp0 = ctx + (long)(b * LL + qbase + warp * 16 + gid) * (NHQ * HD) + h * HD;
        float* cp1 = cp0 + (long)8 * (NHQ * HD);
#pragma unroll
        for (int nt = 0; nt < 8; nt++) {
            const int c0 = nt * 8 + 2 * tig;
            *(float2*)&cp0[c0] = make_float2(o[nt][0] * inv0, o[nt][1] * inv0);
            *(float2*)&cp1[c0] = make_float2(o[nt][2] * inv1, o[nt][3] * inv1);
        }
    }
}

// ---------------------------------------------------------------------------
extern "C" void kernel_launch(void* const* d_in, const int* in_sizes, int n_in,
                              void* d_out, int out_size)
{
    const float* x  = (const float*)d_in[0];
    const float* Wq = (const float*)d_in[1];
    const float* bq = (const float*)d_in[2];
    const float* Wk = (const float*)d_in[3];
    const float* bk = (const float*)d_in[4];
    const float* Wv = (const float*)d_in[5];
    const float* bv = (const float*)d_in[6];
    const float* Wo = (const float*)d_in[7];
    const float* bo = (const float*)d_in[8];
    float* out = (float*)d_out;

    float *gq, *gk, *gv, *gctx;
    cudaGetSymbolAddress((void**)&gq, g_q);
    cudaGetSymbolAddress((void**)&gk, g_k);
    cudaGetSymbolAddress((void**)&gv, g_v);
    cudaGetSymbolAddress((void**)&gctx, g_ctx);

    const int M = BB * LL;   // 4096

    // QKV projections (tf32 tensor cores)
    {
        dim3 gq_grid(NHQ * HD / 128, M / 128);
        sgemm_tf32<<<gq_grid, 256>>>(x, Wq, bq, gq, M, NHQ * HD, DD);
        dim3 gk_grid(NHKV * HD / 128, M / 128);
        sgemm_tf32<<<gk_grid, 256>>>(x, Wk, bk, gk, M, NHKV * HD, DD);
        sgemm_tf32<<<gk_grid, 256>>>(x, Wv, bv, gv, M, NHKV * HD, DD);
    }

    // Attention (tf32 tensor cores, cp.async double buffering)
    {
        const int smem_bytes = (2 * KS_FLOATS + 2 * VS_FLOATS + 64 * PS_STR) * (int)sizeof(float);
        cudaFuncSetAttribute(attn_tf32,
                             cudaFuncAttributeMaxDynamicSharedMemorySize,
                             smem_bytes);
        dim3 grid(LL / 64, NHQ, BB);
        attn_tf32<<<grid, 128, smem_bytes>>>(gq, gk, gv, gctx);
    }

    // Output projection
    {
        dim3 go_grid(DD / 128, M / 128);
        sgemm_tf32<<<go_grid, 256>>>(gctx, Wo, bo, out, M, DD, DD);
    }
}

// round 3
// speedup vs baseline: 3.8788x; 1.9258x over previous
#include <cuda_runtime.h>
#include <cstdint>
#include <math.h>

// Problem constants
#define BB   2
#define LL   2048
#define DD   2048
#define NHQ  32
#define NHKV 8
#define HD   64
#define GRP  4

// Scratch (allocation-free rule: __device__ globals)
__device__ float g_q[BB * LL * NHQ * HD];
__device__ float g_k[BB * LL * NHKV * HD];
__device__ float g_v[BB * LL * NHKV * HD];
__device__ float g_ctx[BB * LL * NHQ * HD];
// tf32-rounded copies of inputs
__device__ float g_x[BB * LL * DD];
__device__ float g_wq[DD * NHQ * HD];
__device__ float g_wk[DD * NHKV * HD];
__device__ float g_wv[DD * NHKV * HD];
__device__ float g_wo[NHQ * HD * DD];

// ---------------------------------------------------------------------------
// helpers
// ---------------------------------------------------------------------------
__device__ __forceinline__ uint32_t f2tf32(float f) {
    uint32_t u;
    asm("cvt.rna.tf32.f32 %0, %1;" : "=r"(u) : "f"(f));
    return u;
}

__device__ __forceinline__ void mma_tf32(float* d, const uint32_t* a, const uint32_t* b) {
    asm volatile(
        "mma.sync.aligned.m16n8k8.row.col.f32.tf32.tf32.f32 "
        "{%0,%1,%2,%3}, {%4,%5,%6,%7}, {%8,%9}, {%0,%1,%2,%3};"
        : "+f"(d[0]), "+f"(d[1]), "+f"(d[2]), "+f"(d[3])
        : "r"(a[0]), "r"(a[1]), "r"(a[2]), "r"(a[3]), "r"(b[0]), "r"(b[1]));
}

__device__ __forceinline__ void cpasync16(uint32_t saddr, const void* g) {
    asm volatile("cp.async.cg.shared.global [%0], [%1], 16;\n" :: "r"(saddr), "l"(g) : "memory");
}
__device__ __forceinline__ void cp_commit() {
    asm volatile("cp.async.commit_group;\n" ::: "memory");
}
template <int N>
__device__ __forceinline__ void cp_wait() {
    asm volatile("cp.async.wait_group %0;\n" :: "n"(N) : "memory");
}

// ---------------------------------------------------------------------------
// elementwise tf32 rounding pass
// ---------------------------------------------------------------------------
__global__ __launch_bounds__(256) void cvt_tf32_kernel(
    const float* __restrict__ in, float* __restrict__ out, int n)
{
    const int i = (blockIdx.x * 256 + threadIdx.x) * 4;
    if (i < n) {
        float4 v = *(const float4*)(in + i);
        v.x = __uint_as_float(f2tf32(v.x));
        v.y = __uint_as_float(f2tf32(v.y));
        v.z = __uint_as_float(f2tf32(v.z));
        v.w = __uint_as_float(f2tf32(v.w));
        *(float4*)(out + i) = v;
    }
}

// ---------------------------------------------------------------------------
// tf32 tensor-core GEMM: C = A @ B + bias. A,B already tf32-rounded.
// 128x128x16 block tile, 3-stage cp.async pipeline, 256 threads,
// warp tile 64x32 (8 warps 2x4). blockIdx.z selects (B,bias,C) pair.
// ---------------------------------------------------------------------------
#define GAS_STR 20
#define GBS_STR 136
#define G_STAGE_A (128 * GAS_STR)              // 2560 floats
#define G_STAGE_B (16 * GBS_STR)               // 2176 floats
#define G_STAGE   (G_STAGE_A + G_STAGE_B)      // 4736 floats

__global__ __launch_bounds__(256) void gemm_tf32(
    const float* __restrict__ A,
    const float* __restrict__ Bm0, const float* __restrict__ Bm1,
    const float* __restrict__ bias0, const float* __restrict__ bias1,
    float* __restrict__ C0, float* __restrict__ C1,
    int M, int N, int K, int cvt_out)
{
    extern __shared__ float sm[];
    const float* Bm  = blockIdx.z ? Bm1 : Bm0;
    const float* bias = blockIdx.z ? bias1 : bias0;
    float* C = blockIdx.z ? C1 : C0;

    const int tid = threadIdx.x;
    const int warp = tid >> 5;
    const int lane = tid & 31;
    const int gid = lane >> 2;
    const int tig = lane & 3;
    const int warp_m = warp >> 2;
    const int warp_n = warp & 3;
    const int bm = blockIdx.y * 128;
    const int bn = blockIdx.x * 128;

    const uint32_t smem_u32 = (uint32_t)__cvta_generic_to_shared(sm);

    // cp.async chunk mapping
    const int a_row0 = tid >> 2;            // chunk c=tid    : row, k4
    const int a_k40 = (tid & 3) << 2;
    const int b_kr0 = tid >> 5;             // chunk c=tid
    const int b_n40 = (tid & 31) << 2;

    auto load_stage = [&](int buf, int k0) {
        const uint32_t abase = smem_u32 + (uint32_t)(buf * G_STAGE) * 4u;
        const uint32_t bbase = abase + (uint32_t)G_STAGE_A * 4u;
        // A: 1024 chunks? no: 128 rows x 4 chunks = 512; threads cover c, c+256
        cpasync16(abase + (a_row0 * GAS_STR + a_k40) * 4,
                  A + (long)(bm + a_row0) * K + k0 + a_k40);
        cpasync16(abase + ((a_row0 + 64) * GAS_STR + a_k40) * 4,
                  A + (long)(bm + a_row0 + 64) * K + k0 + a_k40);
        // B: 16 rows x 32 chunks = 512; threads cover c, c+256
        cpasync16(bbase + (b_kr0 * GBS_STR + b_n40) * 4,
                  Bm + (long)(k0 + b_kr0) * N + bn + b_n40);
        cpasync16(bbase + ((b_kr0 + 8) * GBS_STR + b_n40) * 4,
                  Bm + (long)(k0 + b_kr0 + 8) * N + bn + b_n40);
    };

    float acc[4][4][4];
#pragma unroll
    for (int i = 0; i < 4; i++)
#pragma unroll
        for (int j = 0; j < 4; j++)
#pragma unroll
            for (int r = 0; r < 4; r++) acc[i][j][r] = 0.0f;

    const int nk = K / 16;
    load_stage(0, 0); cp_commit();
    load_stage(1, 16); cp_commit();

#pragma unroll 1
    for (int it = 0; it < nk; ++it) {
        if (it + 1 < nk) cp_wait<1>(); else cp_wait<0>();
        __syncthreads();
        if (it + 2 < nk) { load_stage((it + 2) % 3, (it + 2) * 16); cp_commit(); }

        const float* As = sm + (it % 3) * G_STAGE;
        const float* Bs = As + G_STAGE_A;

#pragma unroll
        for (int ks = 0; ks < 2; ks++) {
            uint32_t af[4][4], bf[4][2];
#pragma unroll
            for (int mt = 0; mt < 4; mt++) {
                const int base = (warp_m * 64 + mt * 16 + gid) * GAS_STR + ks * 8 + tig;
                af[mt][0] = __float_as_uint(As[base]);
                af[mt][1] = __float_as_uint(As[base + 8 * GAS_STR]);
                af[mt][2] = __float_as_uint(As[base + 4]);
                af[mt][3] = __float_as_uint(As[base + 8 * GAS_STR + 4]);
            }
#pragma unroll
            for (int nt = 0; nt < 4; nt++) {
                const int col = warp_n * 32 + nt * 8 + gid;
                bf[nt][0] = __float_as_uint(Bs[(ks * 8 + tig) * GBS_STR + col]);
                bf[nt][1] = __float_as_uint(Bs[(ks * 8 + tig + 4) * GBS_STR + col]);
            }
#pragma unroll
            for (int mt = 0; mt < 4; mt++)
#pragma unroll
                for (int nt = 0; nt < 4; nt++)
                    mma_tf32(acc[mt][nt], af[mt], bf[nt]);
        }
    }

    // epilogue
#pragma unroll
    for (int mt = 0; mt < 4; mt++) {
        const int r0 = bm + warp_m * 64 + mt * 16 + gid;
#pragma unroll
        for (int nt = 0; nt < 4; nt++) {
            const int c0 = bn + warp_n * 32 + nt * 8 + 2 * tig;
            const float bx = bias[c0], by = bias[c0 + 1];
            float v00 = acc[mt][nt][0] + bx, v01 = acc[mt][nt][1] + by;
            float v10 = acc[mt][nt][2] + bx, v11 = acc[mt][nt][3] + by;
            if (cvt_out) {
                v00 = __uint_as_float(f2tf32(v00)); v01 = __uint_as_float(f2tf32(v01));
                v10 = __uint_as_float(f2tf32(v10)); v11 = __uint_as_float(f2tf32(v11));
            }
            *(float2*)&C[(long)r0 * N + c0] = make_float2(v00, v01);
            *(float2*)&C[(long)(r0 + 8) * N + c0] = make_float2(v10, v11);
        }
    }
}

// ---------------------------------------------------------------------------
// tf32 tensor-core flash attention.
// Block: 128 q rows x head x batch. 256 threads (8 warps), warp = 16 q rows.
// K/V (64-row tiles) double-buffered via cp.async; inputs pre-tf32-rounded.
// ---------------------------------------------------------------------------
#define KS_STR 68
#define VS_STR 72
#define PS_STR 68
#define KS_FLOATS (64 * KS_STR)
#define VS_FLOATS (64 * VS_STR)
#define NKT (LL / 64)

__global__ __launch_bounds__(256, 2) void attn_tf32(
    const float* __restrict__ q, const float* __restrict__ k,
    const float* __restrict__ v, float* __restrict__ ctx)
{
    extern __shared__ float sm[];
    float* KsB = sm;                                   // 2 x [64][68]
    float* VsB = sm + 2 * KS_FLOATS;                   // 2 x [64][72]
    float* Ps  = sm + 2 * KS_FLOATS + 2 * VS_FLOATS;   // [128][68]

    const int tid = threadIdx.x;
    const int warp = tid >> 5;
    const int lane = tid & 31;
    const int gid = lane >> 2;
    const int tig = lane & 3;
    const int qt = blockIdx.x;
    const int h  = blockIdx.y;
    const int b  = blockIdx.z;
    const int hk = h >> 2;
    const int qbase = qt * 128;

    const uint32_t ks_s = (uint32_t)__cvta_generic_to_shared(KsB);
    const uint32_t vs_s = (uint32_t)__cvta_generic_to_shared(VsB);

    // Q fragments (already tf32-rounded; *0.125f is exact power of two)
    uint32_t qf[8][4];
    {
        const float* qp = q + (long)(b * LL + qbase + warp * 16 + gid) * (NHQ * HD) + h * HD;
        const float* qp8 = qp + (long)8 * (NHQ * HD);
#pragma unroll
        for (int ks = 0; ks < 8; ks++) {
            const int c = ks * 8 + tig;
            qf[ks][0] = __float_as_uint(qp[c] * 0.125f);
            qf[ks][1] = __float_as_uint(qp8[c] * 0.125f);
            qf[ks][2] = __float_as_uint(qp[c + 4] * 0.125f);
            qf[ks][3] = __float_as_uint(qp8[c + 4] * 0.125f);
        }
    }

    float o[8][4];
    float m[2], l[2];
#pragma unroll
    for (int nt = 0; nt < 8; nt++)
#pragma unroll
        for (int r = 0; r < 4; r++) o[nt][r] = 0.0f;
    m[0] = m[1] = -1e30f;
    l[0] = l[1] = 0.0f;

    const long kvrs = (long)(NHKV * HD);
    const float* kbase = k + (long)(b * LL) * kvrs + hk * HD;
    const float* vbase = v + (long)(b * LL) * kvrs + hk * HD;

    // KV tile loader: 64x64 floats each = 1024 chunks; 256 thr -> 4 chunks per array
    auto load_kv = [&](int buf, int kt) {
#pragma unroll
        for (int j = 0; j < 4; j++) {
            const int c = tid + 256 * j;
            const int row = c >> 4;
            const int c4 = (c & 15) << 2;
            const long goff = (long)(kt * 64 + row) * kvrs + c4;
            cpasync16(ks_s + (buf * KS_FLOATS + row * KS_STR + c4) * 4, kbase + goff);
            cpasync16(vs_s + (buf * VS_FLOATS + row * VS_STR + c4) * 4, vbase + goff);
        }
        cp_commit();
    };

    load_kv(0, 0);

#pragma unroll 1
    for (int kt = 0; kt < NKT; kt++) {
        const int buf = kt & 1;
        if (kt + 1 < NKT) { load_kv(buf ^ 1, kt + 1); cp_wait<1>(); }
        else cp_wait<0>();
        __syncthreads();

        const float* Ks = KsB + buf * KS_FLOATS;
        const float* Vs = VsB + buf * VS_FLOATS;

        // S = Q @ K^T
        float sacc[8][4];
#pragma unroll
        for (int nt = 0; nt < 8; nt++)
#pragma unroll
            for (int r = 0; r < 4; r++) sacc[nt][r] = 0.0f;

#pragma unroll
        for (int ks = 0; ks < 8; ks++) {
            uint32_t bf[8][2];
#pragma unroll
            for (int nt = 0; nt < 8; nt++) {
                const int rowb = (nt * 8 + gid) * KS_STR + ks * 8 + tig;
                bf[nt][0] = __float_as_uint(Ks[rowb]);
                bf[nt][1] = __float_as_uint(Ks[rowb + 4]);
            }
#pragma unroll
            for (int nt = 0; nt < 8; nt++)
                mma_tf32(sacc[nt], qf[ks], bf[nt]);
        }

        // online softmax
#pragma unroll
        for (int i = 0; i < 2; i++) {
            const int r0 = 2 * i;
            float tm = -1e30f;
#pragma unroll
            for (int nt = 0; nt < 8; nt++)
                tm = fmaxf(tm, fmaxf(sacc[nt][r0], sacc[nt][r0 + 1]));
            tm = fmaxf(tm, __shfl_xor_sync(0xffffffffu, tm, 1));
            tm = fmaxf(tm, __shfl_xor_sync(0xffffffffu, tm, 2));
            const float mn = fmaxf(m[i], tm);
            const float alpha = __expf(m[i] - mn);
            m[i] = mn;
            float rs = 0.0f;
            const int prow = (warp * 16 + gid + 8 * i) * PS_STR + 2 * tig;
#pragma unroll
            for (int nt = 0; nt < 8; nt++) {
                float p0 = __expf(sacc[nt][r0] - mn);
                float p1 = __expf(sacc[nt][r0 + 1] - mn);
                rs += p0 + p1;
                Ps[prow + nt * 8]     = __uint_as_float(f2tf32(p0));
                Ps[prow + nt * 8 + 1] = __uint_as_float(f2tf32(p1));
            }
            rs += __shfl_xor_sync(0xffffffffu, rs, 1);
            rs += __shfl_xor_sync(0xffffffffu, rs, 2);
            l[i] = l[i] * alpha + rs;
#pragma unroll
            for (int nt = 0; nt < 8; nt++) {
                o[nt][r0]     *= alpha;
                o[nt][r0 + 1] *= alpha;
            }
        }
        __syncwarp();

        // O += P @ V
#pragma unroll
        for (int ks = 0; ks < 8; ks++) {
            uint32_t pf[4], vf[8][2];
            const int pbase = (warp * 16 + gid) * PS_STR + ks * 8 + tig;
            pf[0] = __float_as_uint(Ps[pbase]);
            pf[1] = __float_as_uint(Ps[pbase + 8 * PS_STR]);
            pf[2] = __float_as_uint(Ps[pbase + 4]);
            pf[3] = __float_as_uint(Ps[pbase + 8 * PS_STR + 4]);
#pragma unroll
            for (int nt = 0; nt < 8; nt++) {
                const int rb = (ks * 8 + tig) * VS_STR + nt * 8 + gid;
                vf[nt][0] = __float_as_uint(Vs[rb]);
                vf[nt][1] = __float_as_uint(Vs[rb + 4 * VS_STR]);
            }
#pragma unroll
            for (int nt = 0; nt < 8; nt++)
                mma_tf32(o[nt], pf, vf[nt]);
        }
        __syncthreads();
    }

    // normalize + store (tf32-rounded: feeds the O projection)
    {
        const float inv0 = 1.0f / l[0];
        const float inv1 = 1.0f / l[1];
        float* cp0 = ctx + (long)(b * LL + qbase + warp * 16 + gid) * (NHQ * HD) + h * HD;
        float* cp1 = cp0 + (long)8 * (NHQ * HD);
#pragma unroll
        for (int nt = 0; nt < 8; nt++) {
            const int c0 = nt * 8 + 2 * tig;
            *(float2*)&cp0[c0] = make_float2(
                __uint_as_float(f2tf32(o[nt][0] * inv0)),
                __uint_as_float(f2tf32(o[nt][1] * inv0)));
            *(float2*)&cp1[c0] = make_float2(
                __uint_as_float(f2tf32(o[nt][2] * inv1)),
                __uint_as_float(f2tf32(o[nt][3] * inv1)));
        }
    }
}

// ---------------------------------------------------------------------------
extern "C" void kernel_launch(void* const* d_in, const int* in_sizes, int n_in,
                              void* d_out, int out_size)
{
    const float* x  = (const float*)d_in[0];
    const float* Wq = (const float*)d_in[1];
    const float* bq = (const float*)d_in[2];
    const float* Wk = (const float*)d_in[3];
    const float* bk = (const float*)d_in[4];
    const float* Wv = (const float*)d_in[5];
    const float* bv = (const float*)d_in[6];
    const float* Wo = (const float*)d_in[7];
    const float* bo = (const float*)d_in[8];
    float* out = (float*)d_out;

    float *gq, *gk, *gv, *gctx, *gx, *gwq, *gwk, *gwv, *gwo;
    cudaGetSymbolAddress((void**)&gq, g_q);
    cudaGetSymbolAddress((void**)&gk, g_k);
    cudaGetSymbolAddress((void**)&gv, g_v);
    cudaGetSymbolAddress((void**)&gctx, g_ctx);
    cudaGetSymbolAddress((void**)&gx, g_x);
    cudaGetSymbolAddress((void**)&gwq, g_wq);
    cudaGetSymbolAddress((void**)&gwk, g_wk);
    cudaGetSymbolAddress((void**)&gwv, g_wv);
    cudaGetSymbolAddress((void**)&gwo, g_wo);

    const int M = BB * LL;

    // tf32 pre-rounding passes
    {
        int nx = BB * LL * DD;
        cvt_tf32_kernel<<<nx / 1024, 256>>>(x, gx, nx);
        int nq = DD * NHQ * HD;
        cvt_tf32_kernel<<<nq / 1024, 256>>>(Wq, gwq, nq);
        int nk = DD * NHKV * HD;
        cvt_tf32_kernel<<<nk / 1024, 256>>>(Wk, gwk, nk);
        cvt_tf32_kernel<<<nk / 1024, 256>>>(Wv, gwv, nk);
        int no = NHQ * HD * DD;
        cvt_tf32_kernel<<<no / 1024, 256>>>(Wo, gwo, no);
    }

    const int gemm_smem = 3 * G_STAGE * (int)sizeof(float);  // 56832
    cudaFuncSetAttribute(gemm_tf32, cudaFuncAttributeMaxDynamicSharedMemorySize, gemm_smem);

    // Q projection
    {
        dim3 grid(NHQ * HD / 128, M / 128, 1);
        gemm_tf32<<<grid, 256, gemm_smem>>>(gx, gwq, gwq, bq, bq, gq, gq,
                                            M, NHQ * HD, DD, 1);
    }
    // K + V projections fused (z-dim)
    {
        dim3 grid(NHKV * HD / 128, M / 128, 2);
        gemm_tf32<<<grid, 256, gemm_smem>>>(gx, gwk, gwv, bk, bv, gk, gv,
                                            M, NHKV * HD, DD, 1);
    }

    // Attention
    {
        const int smem_bytes = (2 * KS_FLOATS + 2 * VS_FLOATS + 128 * PS_STR) * (int)sizeof(float);
        cudaFuncSetAttribute(attn_tf32, cudaFuncAttributeMaxDynamicSharedMemorySize, smem_bytes);
        dim3 grid(LL / 128, NHQ, BB);
        attn_tf32<<<grid, 256, smem_bytes>>>(gq, gk, gv, gctx);
    }

    // Output projection
    {
        dim3 grid(DD / 128, M / 128, 1);
        gemm_tf32<<<grid, 256, gemm_smem>>>(gctx, gwo, gwo, bo, bo, out, out,
                                            M, DD, DD, 0);
    }
}

// round 6
// speedup vs baseline: 6.9849x; 1.8008x over previous
#include <cuda_runtime.h>
#include <cuda_fp16.h>
#include <cstdint>
#include <math.h>

// Problem constants
#define BB   2
#define LL   2048
#define DD   2048
#define NHQ  32
#define NHKV 8
#define HD   64
#define GRP  4

// ---------------------------------------------------------------------------
// Scratch (allocation-free rule: __device__ globals)
// ---------------------------------------------------------------------------
__device__ __half g_xh[BB * LL * DD];              // x fp16
__device__ __half g_wqt[NHQ * HD * DD];            // Wq^T [N][K]
__device__ __half g_wkt[NHKV * HD * DD];
__device__ __half g_wvt[NHKV * HD * DD];
__device__ __half g_wot[DD * NHQ * HD];
__device__ __half g_q[BB * LL * NHQ * HD];         // q fp16 (pre-scaled by 0.125)
__device__ __half g_k[BB * LL * NHKV * HD];        // k fp16
__device__ __half g_vt[BB * NHKV * HD * LL];       // v fp16, [b][hk][d][L]
__device__ __half g_ctx[BB * LL * NHQ * HD];       // attention output fp16

// ---------------------------------------------------------------------------
// helpers
// ---------------------------------------------------------------------------
__device__ __forceinline__ void mma_f16(float* d, const uint32_t* a, const uint32_t* b) {
    asm volatile(
        "mma.sync.aligned.m16n8k16.row.col.f32.f16.f16.f32 "
        "{%0,%1,%2,%3}, {%4,%5,%6,%7}, {%8,%9}, {%0,%1,%2,%3};"
        : "+f"(d[0]), "+f"(d[1]), "+f"(d[2]), "+f"(d[3])
        : "r"(a[0]), "r"(a[1]), "r"(a[2]), "r"(a[3]), "r"(b[0]), "r"(b[1]));
}

// pack two f32 into one f16x2 register (lo = a, hi = b)
__device__ __forceinline__ uint32_t pack_h2(float a, float b) {
    uint32_t r;
    asm("cvt.rn.f16x2.f32 %0, %1, %2;" : "=r"(r) : "f"(b), "f"(a));
    return r;
}

__device__ __forceinline__ void cpasync16(uint32_t saddr, const void* g) {
    asm volatile("cp.async.cg.shared.global [%0], [%1], 16;\n" :: "r"(saddr), "l"(g) : "memory");
}
__device__ __forceinline__ void cp_commit() {
    asm volatile("cp.async.commit_group;\n" ::: "memory");
}
template <int N>
__device__ __forceinline__ void cp_wait() {
    asm volatile("cp.async.wait_group %0;\n" :: "n"(N) : "memory");
}

// ---------------------------------------------------------------------------
// prep: x -> fp16
// ---------------------------------------------------------------------------
__global__ __launch_bounds__(256) void cvt_h_kernel(
    const float* __restrict__ in, __half* __restrict__ out, int n)
{
    const int i = (blockIdx.x * 256 + threadIdx.x) * 4;
    if (i < n) {
        float4 v = *(const float4*)(in + i);
        uint32_t h0 = pack_h2(v.x, v.y);
        uint32_t h1 = pack_h2(v.z, v.w);
        *(uint32_t*)(out + i) = h0;
        *(uint32_t*)(out + i + 2) = h1;
    }
}

// ---------------------------------------------------------------------------
// prep: transpose W[K,N] -> WT[N,K] fp16
// ---------------------------------------------------------------------------
__global__ __launch_bounds__(256) void transpose_h_kernel(
    const float* __restrict__ W, __half* __restrict__ T, int K, int N)
{
    __shared__ float t[32][33];
    const int n0 = blockIdx.x * 32;
    const int k0 = blockIdx.y * 32;
    const int tx = threadIdx.x, ty = threadIdx.y;
#pragma unroll
    for (int i = 0; i < 4; i++)
        t[ty + i * 8][tx] = W[(long)(k0 + ty + i * 8) * N + n0 + tx];
    __syncthreads();
#pragma unroll
    for (int i = 0; i < 4; i++)
        T[(long)(n0 + ty + i * 8) * K + k0 + tx] = __float2half(t[tx][ty + i * 8]);
}

// ---------------------------------------------------------------------------
// fp16 tensor-core GEMM: C[M,N] = A[M,K] @ BT[N,K]^T + bias
// 128x128 tile, K-chunk 32, 3-stage cp.async, 256 threads, warp tile 64x32.
// qkv_mode=1: fused QKV (768 CTAs: 512 Q, 128 K, 128 V-transposed-out).
// qkv_mode=0: O projection, fp32 output (512 CTAs).
// ---------------------------------------------------------------------------
#define GSTR    20                 // 32-bit words per row (16 data + 4 pad)
#define GTILE_W (128 * GSTR)       // 2560 words per operand tile
#define GSTAGE_W (2 * GTILE_W)     // 5120 words = 20 KB
#define GSMEM   (3 * GSTAGE_W * 4) // 61440 B

__global__ __launch_bounds__(256, 2) void gemm_f16(
    const __half* __restrict__ A,
    const __half* __restrict__ Bq, const __half* __restrict__ Bk,
    const __half* __restrict__ Bv,
    const float* __restrict__ bias_q, const float* __restrict__ bias_k,
    const float* __restrict__ bias_v,
    __half* __restrict__ outq, __half* __restrict__ outk,
    __half* __restrict__ outvt, float* __restrict__ outf,
    int qkv_mode)
{
    extern __shared__ uint32_t smw[];
    const uint32_t smb = (uint32_t)__cvta_generic_to_shared(smw);

    int mode, bm, bn;
    if (qkv_mode) {
        const int bx = blockIdx.x;
        if (bx < 512)      { mode = 0; bn = (bx & 15) * 128; bm = (bx >> 4) * 128; }
        else if (bx < 640) { const int t = bx - 512; mode = 1; bn = (t & 3) * 128; bm = (t >> 2) * 128; }
        else               { const int t = bx - 640; mode = 2; bn = (t & 3) * 128; bm = (t >> 2) * 128; }
    } else { mode = 3; bn = (blockIdx.x & 15) * 128; bm = (blockIdx.x >> 4) * 128; }

    const __half* Bm = (mode == 1) ? Bk : (mode == 2) ? Bv : Bq;
    const float* bias = (mode == 1) ? bias_k : (mode == 2) ? bias_v : bias_q;

    const int tid = threadIdx.x;
    const int warp = tid >> 5;
    const int lane = tid & 31;
    const int gid = lane >> 2;
    const int tig = lane & 3;
    const int warp_m = warp >> 2;
    const int warp_n = warp & 3;

    const int l_row = tid >> 2;        // loader row (0..63 base, +64)
    const int l_cc = tid & 3;          // 16B chunk within row

    auto load_stage = [&](int s, int kc) {
        const uint32_t base = smb + (uint32_t)(s * GSTAGE_W) * 4u;
#pragma unroll
        for (int j = 0; j < 2; j++) {
            const int row = l_row + 64 * j;
            cpasync16(base + (row * GSTR + l_cc * 4) * 4,
                      A + (long)(bm + row) * DD + kc + l_cc * 8);
            cpasync16(base + (GTILE_W + row * GSTR + l_cc * 4) * 4,
                      Bm + (long)(bn + row) * DD + kc + l_cc * 8);
        }
        cp_commit();
    };

    float acc[4][4][4];
#pragma unroll
    for (int i = 0; i < 4; i++)
#pragma unroll
        for (int j = 0; j < 4; j++)
#pragma unroll
            for (int r = 0; r < 4; r++) acc[i][j][r] = 0.0f;

    const int nk = DD / 32;   // 64
    load_stage(0, 0);
    load_stage(1, 32);

#pragma unroll 1
    for (int i = 0; i < nk; ++i) {
        const int s = i % 3;
        if (i + 1 < nk) cp_wait<1>(); else cp_wait<0>();
        __syncthreads();
        if (i + 2 < nk) load_stage((i + 2) % 3, (i + 2) * 32);

        const uint32_t* As = smw + s * GSTAGE_W;
        const uint32_t* Bs = As + GTILE_W;

#pragma unroll
        for (int ks = 0; ks < 2; ks++) {
            uint32_t af[4][4], bf[4][2];
#pragma unroll
            for (int mt = 0; mt < 4; mt++) {
                const int base = (warp_m * 64 + mt * 16 + gid) * GSTR + ks * 8 + tig;
                af[mt][0] = As[base];
                af[mt][1] = As[base + 8 * GSTR];
                af[mt][2] = As[base + 4];
                af[mt][3] = As[base + 8 * GSTR + 4];
            }
#pragma unroll
            for (int nt = 0; nt < 4; nt++) {
                const int nb = (warp_n * 32 + nt * 8 + gid) * GSTR + ks * 8 + tig;
                bf[nt][0] = Bs[nb];
                bf[nt][1] = Bs[nb + 4];
            }
#pragma unroll
            for (int mt = 0; mt < 4; mt++)
#pragma unroll
                for (int nt = 0; nt < 4; nt++)
                    mma_f16(acc[mt][nt], af[mt], bf[nt]);
        }
    }

    // epilogue
#pragma unroll
    for (int mt = 0; mt < 4; mt++) {
        const int r = bm + warp_m * 64 + mt * 16 + gid;
#pragma unroll
        for (int nt = 0; nt < 4; nt++) {
            const int c = bn + warp_n * 32 + nt * 8 + 2 * tig;
            const float bx0 = bias[c], bx1 = bias[c + 1];
            float v00 = acc[mt][nt][0] + bx0, v01 = acc[mt][nt][1] + bx1;
            float v10 = acc[mt][nt][2] + bx0, v11 = acc[mt][nt][3] + bx1;
            if (mode == 0) {          // Q: scale by 1/8, fp16
                *(uint32_t*)(outq + (long)r * 2048 + c) =
                    pack_h2(v00 * 0.125f, v01 * 0.125f);
                *(uint32_t*)(outq + (long)(r + 8) * 2048 + c) =
                    pack_h2(v10 * 0.125f, v11 * 0.125f);
            } else if (mode == 1) {   // K: fp16
                *(uint32_t*)(outk + (long)r * 512 + c) = pack_h2(v00, v01);
                *(uint32_t*)(outk + (long)(r + 8) * 512 + c) = pack_h2(v10, v11);
            } else if (mode == 2) {   // V: fp16 transposed [b][hk][d][L]
                const int hk = c >> 6, d = c & 63;
                const int bb = r >> 11, lrow = r & 2047;
                const long base = ((long)(bb * NHKV + hk) * HD + d) * LL + lrow;
                outvt[base] = __float2half(v00);
                outvt[base + LL] = __float2half(v01);
                outvt[base + 8] = __float2half(v10);
                outvt[base + LL + 8] = __float2half(v11);
            } else {                  // O: fp32 out
                *(float2*)(outf + (long)r * 2048 + c) = make_float2(v00, v01);
                *(float2*)(outf + (long)(r + 8) * 2048 + c) = make_float2(v10, v11);
            }
        }
    }
}

// ---------------------------------------------------------------------------
// fp16 tensor-core flash attention.
// Block: 128 q rows x head x batch. 256 threads (8 warps), warp = 16 q rows.
// K (row-major) and V (pre-transposed [d][L]) double-buffered via cp.async.
// smem words: Ks 2x[64][36], Vs 2x[64][36], Ps [128][36].
// ---------------------------------------------------------------------------
#define ASTR 36                         // words per row (32 data + 4 pad)
#define KT_W (64 * ASTR)                // 2304 words per K/V buffer
#define ATT_SMEM ((4 * KT_W + 128 * ASTR) * 4)   // 55296 B
#define NKT (LL / 64)

__global__ __launch_bounds__(256, 2) void attn_f16(
    const __half* __restrict__ q, const __half* __restrict__ k,
    const __half* __restrict__ vt, __half* __restrict__ ctx)
{
    extern __shared__ uint32_t smw[];
    uint32_t* KsW = smw;                 // 2 x [64][36]
    uint32_t* VsW = smw + 2 * KT_W;      // 2 x [64][36]
    uint32_t* PsW = smw + 4 * KT_W;      // [128][36]
    const uint32_t ks_s = (uint32_t)__cvta_generic_to_shared(KsW);
    const uint32_t vs_s = (uint32_t)__cvta_generic_to_shared(VsW);

    const int tid = threadIdx.x;
    const int warp = tid >> 5;
    const int lane = tid & 31;
    const int gid = lane >> 2;
    const int tig = lane & 3;
    const int qt = blockIdx.x;
    const int h  = blockIdx.y;
    const int b  = blockIdx.z;
    const int hk = h >> 2;
    const int qbase = qt * 128;

    // Q fragments (fp16, pre-scaled). 4 k16-steps over HD=64.
    uint32_t qf[4][4];
    {
        const __half* qp = q + (long)(b * LL + qbase + warp * 16 + gid) * (NHQ * HD) + h * HD;
        const __half* qp8 = qp + (long)8 * (NHQ * HD);
#pragma unroll
        for (int ks = 0; ks < 4; ks++) {
            const int c = ks * 16 + 2 * tig;
            qf[ks][0] = *(const uint32_t*)(qp + c);
            qf[ks][1] = *(const uint32_t*)(qp8 + c);
            qf[ks][2] = *(const uint32_t*)(qp + c + 8);
            qf[ks][3] = *(const uint32_t*)(qp8 + c + 8);
        }
    }

    float o[8][4];
    float m[2], l[2];
#pragma unroll
    for (int nt = 0; nt < 8; nt++)
#pragma unroll
        for (int r = 0; r < 4; r++) o[nt][r] = 0.0f;
    m[0] = m[1] = -1e30f;
    l[0] = l[1] = 0.0f;

    const __half* kbase = k + (long)(b * LL) * (NHKV * HD) + hk * HD;
    const __half* vbase = vt + (long)(b * NHKV + hk) * HD * LL;

    // loader: K tile rows=kcol (64 x 128B), V tile rows=d (64 x 128B); 2 chunks each per thread
    auto load_kv = [&](int buf, int kt) {
#pragma unroll
        for (int j = 0; j < 2; j++) {
            const int c = tid + 256 * j;
            const int row = c >> 3;
            const int cc = c & 7;
            cpasync16(ks_s + ((buf * KT_W) + row * ASTR + cc * 4) * 4,
                      kbase + (long)(kt * 64 + row) * (NHKV * HD) + cc * 8);
            cpasync16(vs_s + ((buf * KT_W) + row * ASTR + cc * 4) * 4,
                      vbase + (long)row * LL + kt * 64 + cc * 8);
        }
        cp_commit();
    };

    load_kv(0, 0);

#pragma unroll 1
    for (int kt = 0; kt < NKT; kt++) {
        const int buf = kt & 1;
        if (kt + 1 < NKT) { load_kv(buf ^ 1, kt + 1); cp_wait<1>(); }
        else cp_wait<0>();
        __syncthreads();

        const uint32_t* Ks = KsW + buf * KT_W;
        const uint32_t* Vs = VsW + buf * KT_W;

        // ---- S = Q @ K^T ----
        float sacc[8][4];
#pragma unroll
        for (int nt = 0; nt < 8; nt++)
#pragma unroll
            for (int r = 0; r < 4; r++) sacc[nt][r] = 0.0f;

#pragma unroll
        for (int ks = 0; ks < 4; ks++) {
            uint32_t bf[8][2];
#pragma unroll
            for (int nt = 0; nt < 8; nt++) {
                const int nb = (nt * 8 + gid) * ASTR + ks * 8 + tig;
                bf[nt][0] = Ks[nb];
                bf[nt][1] = Ks[nb + 4];
            }
#pragma unroll
            for (int nt = 0; nt < 8; nt++)
                mma_f16(sacc[nt], qf[ks], bf[nt]);
        }

        // ---- online softmax (rows gid, gid+8) ----
#pragma unroll
        for (int i = 0; i < 2; i++) {
            const int r0 = 2 * i;
            float tm = -1e30f;
#pragma unroll
            for (int nt = 0; nt < 8; nt++)
                tm = fmaxf(tm, fmaxf(sacc[nt][r0], sacc[nt][r0 + 1]));
            tm = fmaxf(tm, __shfl_xor_sync(0xffffffffu, tm, 1));
            tm = fmaxf(tm, __shfl_xor_sync(0xffffffffu, tm, 2));
            const float mn = fmaxf(m[i], tm);
            const float alpha = __expf(m[i] - mn);
            m[i] = mn;
            float rs = 0.0f;
            const int prow = (warp * 16 + gid + 8 * i) * ASTR + tig;
#pragma unroll
            for (int nt = 0; nt < 8; nt++) {
                float p0 = __expf(sacc[nt][r0] - mn);
                float p1 = __expf(sacc[nt][r0 + 1] - mn);
                rs += p0 + p1;
                PsW[prow + nt * 4] = pack_h2(p0, p1);
            }
            rs += __shfl_xor_sync(0xffffffffu, rs, 1);
            rs += __shfl_xor_sync(0xffffffffu, rs, 2);
            l[i] = l[i] * alpha + rs;
#pragma unroll
            for (int nt = 0; nt < 8; nt++) {
                o[nt][r0]     *= alpha;
                o[nt][r0 + 1] *= alpha;
            }
        }
        __syncwarp();

        // ---- O += P @ V  (n = d, 64 wide) ----
#pragma unroll
        for (int ks = 0; ks < 4; ks++) {
            uint32_t pf[4], vf[8][2];
            const int pb = (warp * 16 + gid) * ASTR + ks * 8 + tig;
            pf[0] = PsW[pb];
            pf[1] = PsW[pb + 8 * ASTR];
            pf[2] = PsW[pb + 4];
            pf[3] = PsW[pb + 8 * ASTR + 4];
#pragma unroll
            for (int nt = 0; nt < 8; nt++) {
                const int vb = (nt * 8 + gid) * ASTR + ks * 8 + tig;
                vf[nt][0] = Vs[vb];
                vf[nt][1] = Vs[vb + 4];
            }
#pragma unroll
            for (int nt = 0; nt < 8; nt++)
                mma_f16(o[nt], pf, vf[nt]);
        }
        __syncthreads();
    }

    // ---- normalize + fp16 store ----
    {
        const float inv0 = 1.0f / l[0];
        const float inv1 = 1.0f / l[1];
        __half* cp0 = ctx + (long)(b * LL + qbase + warp * 16 + gid) * (NHQ * HD) + h * HD;
        __half* cp1 = cp0 + (long)8 * (NHQ * HD);
#pragma unroll
        for (int nt = 0; nt < 8; nt++) {
            const int c0 = nt * 8 + 2 * tig;
            *(uint32_t*)(cp0 + c0) = pack_h2(o[nt][0] * inv0, o[nt][1] * inv0);
            *(uint32_t*)(cp1 + c0) = pack_h2(o[nt][2] * inv1, o[nt][3] * inv1);
        }
    }
}

// ---------------------------------------------------------------------------
extern "C" void kernel_launch(void* const* d_in, const int* in_sizes, int n_in,
                              void* d_out, int out_size)
{
    const float* x  = (const float*)d_in[0];
    const float* Wq = (const float*)d_in[1];
    const float* bq = (const float*)d_in[2];
    const float* Wk = (const float*)d_in[3];
    const float* bk = (const float*)d_in[4];
    const float* Wv = (const float*)d_in[5];
    const float* bv = (const float*)d_in[6];
    const float* Wo = (const float*)d_in[7];
    const float* bo = (const float*)d_in[8];
    float* out = (float*)d_out;

    __half *gxh, *gwqt, *gwkt, *gwvt, *gwot, *gq, *gk, *gvt, *gctx;
    cudaGetSymbolAddress((void**)&gxh, g_xh);
    cudaGetSymbolAddress((void**)&gwqt, g_wqt);
    cudaGetSymbolAddress((void**)&gwkt, g_wkt);
    cudaGetSymbolAddress((void**)&gwvt, g_wvt);
    cudaGetSymbolAddress((void**)&gwot, g_wot);
    cudaGetSymbolAddress((void**)&gq, g_q);
    cudaGetSymbolAddress((void**)&gk, g_k);
    cudaGetSymbolAddress((void**)&gvt, g_vt);
    cudaGetSymbolAddress((void**)&gctx, g_ctx);

    const int M = BB * LL;   // 4096

    // prep
    {
        const int nx = M * DD;
        cvt_h_kernel<<<nx / 1024, 256>>>(x, gxh, nx);
        dim3 blk(32, 8);
        transpose_h_kernel<<<dim3((NHQ * HD) / 32, DD / 32), blk>>>(Wq, gwqt, DD, NHQ * HD);
        transpose_h_kernel<<<dim3((NHKV * HD) / 32, DD / 32), blk>>>(Wk, gwkt, DD, NHKV * HD);
        transpose_h_kernel<<<dim3((NHKV * HD) / 32, DD / 32), blk>>>(Wv, gwvt, DD, NHKV * HD);
        transpose_h_kernel<<<dim3(DD / 32, (NHQ * HD) / 32), blk>>>(Wo, gwot, NHQ * HD, DD);
    }

    cudaFuncSetAttribute(gemm_f16, cudaFuncAttributeMaxDynamicSharedMemorySize, GSMEM);
    cudaFuncSetAttribute(attn_f16, cudaFuncAttributeMaxDynamicSharedMemorySize, ATT_SMEM);

    // fused QKV projections
    gemm_f16<<<768, 256, GSMEM>>>(gxh, gwqt, gwkt, gwvt, bq, bk, bv,
                                  gq, gk, gvt, out, 1);

    // attention
    {
        dim3 grid(LL / 128, NHQ, BB);
        attn_f16<<<grid, 256, ATT_SMEM>>>(gq, gk, gvt, gctx);
    }

    // O projection (fp32 out)
    gemm_f16<<<512, 256, GSMEM>>>(gctx, gwot, gwot, gwot, bo, bo, bo,
                                  gq, gk, gvt, out, 0);
}

// round 7
// speedup vs baseline: 7.6117x; 1.0897x over previous
#include <cuda_runtime.h>
#include <cuda_fp16.h>
#include <cstdint>
#include <math.h>

// Problem constants
#define BB   2
#define LL   2048
#define DD   2048
#define NHQ  32
#define NHKV 8
#define HD   64
#define GRP  4

// ---------------------------------------------------------------------------
// Scratch (allocation-free rule: __device__ globals)
// ---------------------------------------------------------------------------
__device__ __half g_xh[BB * LL * DD];              // x fp16
__device__ __half g_wqt[NHQ * HD * DD];            // Wq^T [N][K]
__device__ __half g_wkt[NHKV * HD * DD];
__device__ __half g_wvt[NHKV * HD * DD];
__device__ __half g_wot[DD * NHQ * HD];
__device__ __half g_q[BB * LL * NHQ * HD];         // q fp16 (pre-scaled by 0.125)
__device__ __half g_k[BB * LL * NHKV * HD];        // k fp16
__device__ __half g_vt[BB * NHKV * HD * LL];       // v fp16, [b][hk][d][L]
__device__ __half g_ctx[BB * LL * NHQ * HD];       // attention output fp16

// ---------------------------------------------------------------------------
// helpers
// ---------------------------------------------------------------------------
__device__ __forceinline__ void mma_f16(float* d, const uint32_t* a, const uint32_t* b) {
    asm volatile(
        "mma.sync.aligned.m16n8k16.row.col.f32.f16.f16.f32 "
        "{%0,%1,%2,%3}, {%4,%5,%6,%7}, {%8,%9}, {%0,%1,%2,%3};"
        : "+f"(d[0]), "+f"(d[1]), "+f"(d[2]), "+f"(d[3])
        : "r"(a[0]), "r"(a[1]), "r"(a[2]), "r"(a[3]), "r"(b[0]), "r"(b[1]));
}

// pack two f32 into one f16x2 register (lo = a, hi = b)
__device__ __forceinline__ uint32_t pack_h2(float a, float b) {
    uint32_t r;
    asm("cvt.rn.f16x2.f32 %0, %1, %2;" : "=r"(r) : "f"(b), "f"(a));
    return r;
}

// ldmatrix x4: 4 8x8 fp16 tiles; per-thread addr selects row of tile (lane>>3)
__device__ __forceinline__ void ldsm_x4(uint32_t& r0, uint32_t& r1, uint32_t& r2,
                                        uint32_t& r3, uint32_t addr) {
    asm volatile("ldmatrix.sync.aligned.m8n8.x4.shared.b16 {%0,%1,%2,%3}, [%4];"
                 : "=r"(r0), "=r"(r1), "=r"(r2), "=r"(r3) : "r"(addr));
}

__device__ __forceinline__ void cpasync16(uint32_t saddr, const void* g) {
    asm volatile("cp.async.cg.shared.global [%0], [%1], 16;\n" :: "r"(saddr), "l"(g) : "memory");
}
__device__ __forceinline__ void cp_commit() {
    asm volatile("cp.async.commit_group;\n" ::: "memory");
}
template <int N>
__device__ __forceinline__ void cp_wait() {
    asm volatile("cp.async.wait_group %0;\n" :: "n"(N) : "memory");
}

// ---------------------------------------------------------------------------
// prep: x -> fp16
// ---------------------------------------------------------------------------
__global__ __launch_bounds__(256) void cvt_h_kernel(
    const float* __restrict__ in, __half* __restrict__ out, int n)
{
    const int i = (blockIdx.x * 256 + threadIdx.x) * 4;
    if (i < n) {
        float4 v = *(const float4*)(in + i);
        uint32_t h0 = pack_h2(v.x, v.y);
        uint32_t h1 = pack_h2(v.z, v.w);
        *(uint32_t*)(out + i) = h0;
        *(uint32_t*)(out + i + 2) = h1;
    }
}

// ---------------------------------------------------------------------------
// prep: transpose W[K,N] -> WT[N,K] fp16
// ---------------------------------------------------------------------------
__global__ __launch_bounds__(256) void transpose_h_kernel(
    const float* __restrict__ W, __half* __restrict__ T, int K, int N)
{
    __shared__ float t[32][33];
    const int n0 = blockIdx.x * 32;
    const int k0 = blockIdx.y * 32;
    const int tx = threadIdx.x, ty = threadIdx.y;
#pragma unroll
    for (int i = 0; i < 4; i++)
        t[ty + i * 8][tx] = W[(long)(k0 + ty + i * 8) * N + n0 + tx];
    __syncthreads();
#pragma unroll
    for (int i = 0; i < 4; i++)
        T[(long)(n0 + ty + i * 8) * K + k0 + tx] = __float2half(t[tx][ty + i * 8]);
}

// ---------------------------------------------------------------------------
// fp16 tensor-core GEMM: C[M,N] = A[M,K] @ BT[N,K]^T + bias
// 128x128 tile, K-chunk 32, 3-stage cp.async, 256 threads, warp tile 64x32.
// Fragment loads via ldmatrix.x4 (conflict-free at GSTR=20).
// ---------------------------------------------------------------------------
#define GSTR    20                 // 32-bit words per row (16 data + 4 pad)
#define GTILE_W (128 * GSTR)       // 2560 words per operand tile
#define GSTAGE_W (2 * GTILE_W)     // 5120 words = 20 KB
#define GSMEM   (3 * GSTAGE_W * 4) // 61440 B

__global__ __launch_bounds__(256, 2) void gemm_f16(
    const __half* __restrict__ A,
    const __half* __restrict__ Bq, const __half* __restrict__ Bk,
    const __half* __restrict__ Bv,
    const float* __restrict__ bias_q, const float* __restrict__ bias_k,
    const float* __restrict__ bias_v,
    __half* __restrict__ outq, __half* __restrict__ outk,
    __half* __restrict__ outvt, float* __restrict__ outf,
    int qkv_mode)
{
    extern __shared__ uint32_t smw[];
    const uint32_t smb = (uint32_t)__cvta_generic_to_shared(smw);

    int mode, bm, bn;
    if (qkv_mode) {
        const int bx = blockIdx.x;
        if (bx < 512)      { mode = 0; bn = (bx & 15) * 128; bm = (bx >> 4) * 128; }
        else if (bx < 640) { const int t = bx - 512; mode = 1; bn = (t & 3) * 128; bm = (t >> 2) * 128; }
        else               { const int t = bx - 640; mode = 2; bn = (t & 3) * 128; bm = (t >> 2) * 128; }
    } else { mode = 3; bn = (blockIdx.x & 15) * 128; bm = (blockIdx.x >> 4) * 128; }

    const __half* Bm = (mode == 1) ? Bk : (mode == 2) ? Bv : Bq;
    const float* bias = (mode == 1) ? bias_k : (mode == 2) ? bias_v : bias_q;

    const int tid = threadIdx.x;
    const int warp = tid >> 5;
    const int lane = tid & 31;
    const int gid = lane >> 2;
    const int tig = lane & 3;
    const int warp_m = warp >> 2;
    const int warp_n = warp & 3;
    const int r8 = lane & 7;
    const int qd = lane >> 3;       // ldmatrix quadrant

    const int l_row = tid >> 2;
    const int l_cc = tid & 3;

    auto load_stage = [&](int s, int kc) {
        const uint32_t base = smb + (uint32_t)(s * GSTAGE_W) * 4u;
#pragma unroll
        for (int j = 0; j < 2; j++) {
            const int row = l_row + 64 * j;
            cpasync16(base + (row * GSTR + l_cc * 4) * 4,
                      A + (long)(bm + row) * DD + kc + l_cc * 8);
            cpasync16(base + (GTILE_W + row * GSTR + l_cc * 4) * 4,
                      Bm + (long)(bn + row) * DD + kc + l_cc * 8);
        }
        cp_commit();
    };

    float acc[4][4][4];
#pragma unroll
    for (int i = 0; i < 4; i++)
#pragma unroll
        for (int j = 0; j < 4; j++)
#pragma unroll
            for (int r = 0; r < 4; r++) acc[i][j][r] = 0.0f;

    // ldmatrix per-thread row components (A-type: row += (qd&1)*8, col += (qd>>1)*8h)
    const int a_row_l = warp_m * 64 + (qd & 1) * 8 + r8;
    const int a_col_l = (qd >> 1) * 4;                    // words
    // B-type pair load: row += (qd>>1)*8, col += (qd&1)*8h
    const int b_row_l = warp_n * 32 + (qd >> 1) * 8 + r8;
    const int b_col_l = (qd & 1) * 4;                     // words

    const int nk = DD / 32;   // 64
    load_stage(0, 0);
    load_stage(1, 32);

#pragma unroll 1
    for (int i = 0; i < nk; ++i) {
        const int s = i % 3;
        if (i + 1 < nk) cp_wait<1>(); else cp_wait<0>();
        __syncthreads();
        if (i + 2 < nk) load_stage((i + 2) % 3, (i + 2) * 32);

        const uint32_t abase = smb + (uint32_t)(s * GSTAGE_W) * 4u;
        const uint32_t bbase = abase + (uint32_t)GTILE_W * 4u;

#pragma unroll
        for (int ks = 0; ks < 2; ks++) {
            uint32_t af[4][4], bf[4][2];
#pragma unroll
            for (int mt = 0; mt < 4; mt++)
                ldsm_x4(af[mt][0], af[mt][1], af[mt][2], af[mt][3],
                        abase + ((a_row_l + mt * 16) * GSTR + ks * 8 + a_col_l) * 4);
#pragma unroll
            for (int p = 0; p < 4; p += 2)
                ldsm_x4(bf[p][0], bf[p][1], bf[p + 1][0], bf[p + 1][1],
                        bbase + ((b_row_l + p * 8) * GSTR + ks * 8 + b_col_l) * 4);
#pragma unroll
            for (int mt = 0; mt < 4; mt++)
#pragma unroll
                for (int nt = 0; nt < 4; nt++)
                    mma_f16(acc[mt][nt], af[mt], bf[nt]);
        }
    }

    // epilogue
#pragma unroll
    for (int mt = 0; mt < 4; mt++) {
        const int r = bm + warp_m * 64 + mt * 16 + gid;
#pragma unroll
        for (int nt = 0; nt < 4; nt++) {
            const int c = bn + warp_n * 32 + nt * 8 + 2 * tig;
            const float bx0 = bias[c], bx1 = bias[c + 1];
            float v00 = acc[mt][nt][0] + bx0, v01 = acc[mt][nt][1] + bx1;
            float v10 = acc[mt][nt][2] + bx0, v11 = acc[mt][nt][3] + bx1;
            if (mode == 0) {          // Q: scale by 1/8, fp16
                *(uint32_t*)(outq + (long)r * 2048 + c) =
                    pack_h2(v00 * 0.125f, v01 * 0.125f);
                *(uint32_t*)(outq + (long)(r + 8) * 2048 + c) =
                    pack_h2(v10 * 0.125f, v11 * 0.125f);
            } else if (mode == 1) {   // K: fp16
                *(uint32_t*)(outk + (long)r * 512 + c) = pack_h2(v00, v01);
                *(uint32_t*)(outk + (long)(r + 8) * 512 + c) = pack_h2(v10, v11);
            } else if (mode == 2) {   // V: fp16 transposed [b][hk][d][L]
                const int hk = c >> 6, d = c & 63;
                const int bb = r >> 11, lrow = r & 2047;
                const long base = ((long)(bb * NHKV + hk) * HD + d) * LL + lrow;
                outvt[base] = __float2half(v00);
                outvt[base + LL] = __float2half(v01);
                outvt[base + 8] = __float2half(v10);
                outvt[base + LL + 8] = __float2half(v11);
            } else {                  // O: fp32 out
                *(float2*)(outf + (long)r * 2048 + c) = make_float2(v00, v01);
                *(float2*)(outf + (long)(r + 8) * 2048 + c) = make_float2(v10, v11);
            }
        }
    }
}

// ---------------------------------------------------------------------------
// fp16 tensor-core flash attention, ldmatrix fragment loads.
// Block: 128 q rows x head x batch. 256 threads (8 warps), warp = 16 q rows.
// ---------------------------------------------------------------------------
#define ASTR 36                         // words per row (32 data + 4 pad)
#define KT_W (64 * ASTR)                // 2304 words per K/V buffer
#define ATT_SMEM ((4 * KT_W + 128 * ASTR) * 4)   // 55296 B
#define NKT (LL / 64)

__global__ __launch_bounds__(256, 2) void attn_f16(
    const __half* __restrict__ q, const __half* __restrict__ k,
    const __half* __restrict__ vt, __half* __restrict__ ctx)
{
    extern __shared__ uint32_t smw[];
    uint32_t* KsW = smw;                 // 2 x [64][36]
    uint32_t* VsW = smw + 2 * KT_W;      // 2 x [64][36]
    uint32_t* PsW = smw + 4 * KT_W;      // [128][36]
    const uint32_t ks_s = (uint32_t)__cvta_generic_to_shared(KsW);
    const uint32_t vs_s = (uint32_t)__cvta_generic_to_shared(VsW);
    const uint32_t ps_s = (uint32_t)__cvta_generic_to_shared(PsW);

    const int tid = threadIdx.x;
    const int warp = tid >> 5;
    const int lane = tid & 31;
    const int gid = lane >> 2;
    const int tig = lane & 3;
    const int r8 = lane & 7;
    const int qd = lane >> 3;
    const int qt = blockIdx.x;
    const int h  = blockIdx.y;
    const int b  = blockIdx.z;
    const int hk = h >> 2;
    const int qbase = qt * 128;

    // ldmatrix row/col components
    const int bt_row = (qd >> 1) * 8 + r8;   // B-type (K/V): row within 16-row pair
    const int bt_col = (qd & 1) * 4;         // words
    const int at_row = warp * 16 + (qd & 1) * 8 + r8;  // A-type (P)
    const int at_col = (qd >> 1) * 4;        // words

    // Q fragments (fp16, pre-scaled). 4 k16-steps over HD=64.
    uint32_t qf[4][4];
    {
        const __half* qp = q + (long)(b * LL + qbase + warp * 16 + gid) * (NHQ * HD) + h * HD;
        const __half* qp8 = qp + (long)8 * (NHQ * HD);
#pragma unroll
        for (int ks = 0; ks < 4; ks++) {
            const int c = ks * 16 + 2 * tig;
            qf[ks][0] = *(const uint32_t*)(qp + c);
            qf[ks][1] = *(const uint32_t*)(qp8 + c);
            qf[ks][2] = *(const uint32_t*)(qp + c + 8);
            qf[ks][3] = *(const uint32_t*)(qp8 + c + 8);
        }
    }

    float o[8][4];
    float m[2], l[2];
#pragma unroll
    for (int nt = 0; nt < 8; nt++)
#pragma unroll
        for (int r = 0; r < 4; r++) o[nt][r] = 0.0f;
    m[0] = m[1] = -1e30f;
    l[0] = l[1] = 0.0f;

    const __half* kbase = k + (long)(b * LL) * (NHKV * HD) + hk * HD;
    const __half* vbase = vt + (long)(b * NHKV + hk) * HD * LL;

    auto load_kv = [&](int buf, int kt) {
#pragma unroll
        for (int j = 0; j < 2; j++) {
            const int c = tid + 256 * j;
            const int row = c >> 3;
            const int cc = c & 7;
            cpasync16(ks_s + ((buf * KT_W) + row * ASTR + cc * 4) * 4,
                      kbase + (long)(kt * 64 + row) * (NHKV * HD) + cc * 8);
            cpasync16(vs_s + ((buf * KT_W) + row * ASTR + cc * 4) * 4,
                      vbase + (long)row * LL + kt * 64 + cc * 8);
        }
        cp_commit();
    };

    load_kv(0, 0);

#pragma unroll 1
    for (int kt = 0; kt < NKT; kt++) {
        const int buf = kt & 1;
        if (kt + 1 < NKT) { load_kv(buf ^ 1, kt + 1); cp_wait<1>(); }
        else cp_wait<0>();
        __syncthreads();

        const uint32_t kb = ks_s + (uint32_t)(buf * KT_W) * 4u;
        const uint32_t vb = vs_s + (uint32_t)(buf * KT_W) * 4u;

        // ---- S = Q @ K^T ----
        float sacc[8][4];
#pragma unroll
        for (int nt = 0; nt < 8; nt++)
#pragma unroll
            for (int r = 0; r < 4; r++) sacc[nt][r] = 0.0f;

#pragma unroll
        for (int ks = 0; ks < 4; ks++) {
            uint32_t bf[8][2];
#pragma unroll
            for (int p = 0; p < 8; p += 2)
                ldsm_x4(bf[p][0], bf[p][1], bf[p + 1][0], bf[p + 1][1],
                        kb + ((p * 8 + bt_row) * ASTR + ks * 8 + bt_col) * 4);
#pragma unroll
            for (int nt = 0; nt < 8; nt++)
                mma_f16(sacc[nt], qf[ks], bf[nt]);
        }

        // ---- online softmax (rows gid, gid+8) ----
#pragma unroll
        for (int i = 0; i < 2; i++) {
            const int r0 = 2 * i;
            float tm = -1e30f;
#pragma unroll
            for (int nt = 0; nt < 8; nt++)
                tm = fmaxf(tm, fmaxf(sacc[nt][r0], sacc[nt][r0 + 1]));
            tm = fmaxf(tm, __shfl_xor_sync(0xffffffffu, tm, 1));
            tm = fmaxf(tm, __shfl_xor_sync(0xffffffffu, tm, 2));
            const float mn = fmaxf(m[i], tm);
            const float alpha = __expf(m[i] - mn);
            m[i] = mn;
            float rs = 0.0f;
            const int prow = (warp * 16 + gid + 8 * i) * ASTR + tig;
#pragma unroll
            for (int nt = 0; nt < 8; nt++) {
                float p0 = __expf(sacc[nt][r0] - mn);
                float p1 = __expf(sacc[nt][r0 + 1] - mn);
                rs += p0 + p1;
                PsW[prow + nt * 4] = pack_h2(p0, p1);
            }
            rs += __shfl_xor_sync(0xffffffffu, rs, 1);
            rs += __shfl_xor_sync(0xffffffffu, rs, 2);
            l[i] = l[i] * alpha + rs;
#pragma unroll
            for (int nt = 0; nt < 8; nt++) {
                o[nt][r0]     *= alpha;
                o[nt][r0 + 1] *= alpha;
            }
        }
        __syncwarp();

        // ---- O += P @ V  (n = d, 64 wide) ----
#pragma unroll
        for (int ks = 0; ks < 4; ks++) {
            uint32_t pf[4], vf[8][2];
            ldsm_x4(pf[0], pf[1], pf[2], pf[3],
                    ps_s + (at_row * ASTR + ks * 8 + at_col) * 4);
#pragma unroll
            for (int p = 0; p < 8; p += 2)
                ldsm_x4(vf[p][0], vf[p][1], vf[p + 1][0], vf[p + 1][1],
                        vb + ((p * 8 + bt_row) * ASTR + ks * 8 + bt_col) * 4);
#pragma unroll
            for (int nt = 0; nt < 8; nt++)
                mma_f16(o[nt], pf, vf[nt]);
        }
        __syncthreads();
    }

    // ---- normalize + fp16 store ----
    {
        const float inv0 = 1.0f / l[0];
        const float inv1 = 1.0f / l[1];
        __half* cp0 = ctx + (long)(b * LL + qbase + warp * 16 + gid) * (NHQ * HD) + h * HD;
        __half* cp1 = cp0 + (long)8 * (NHQ * HD);
#pragma unroll
        for (int nt = 0; nt < 8; nt++) {
            const int c0 = nt * 8 + 2 * tig;
            *(uint32_t*)(cp0 + c0) = pack_h2(o[nt][0] * inv0, o[nt][1] * inv0);
            *(uint32_t*)(cp1 + c0) = pack_h2(o[nt][2] * inv1, o[nt][3] * inv1);
        }
    }
}

// ---------------------------------------------------------------------------
extern "C" void kernel_launch(void* const* d_in, const int* in_sizes, int n_in,
                              void* d_out, int out_size)
{
    const float* x  = (const float*)d_in[0];
    const float* Wq = (const float*)d_in[1];
    const float* bq = (const float*)d_in[2];
    const float* Wk = (const float*)d_in[3];
    const float* bk = (const float*)d_in[4];
    const float* Wv = (const float*)d_in[5];
    const float* bv = (const float*)d_in[6];
    const float* Wo = (const float*)d_in[7];
    const float* bo = (const float*)d_in[8];
    float* out = (float*)d_out;

    __half *gxh, *gwqt, *gwkt, *gwvt, *gwot, *gq, *gk, *gvt, *gctx;
    cudaGetSymbolAddress((void**)&gxh, g_xh);
    cudaGetSymbolAddress((void**)&gwqt, g_wqt);
    cudaGetSymbolAddress((void**)&gwkt, g_wkt);
    cudaGetSymbolAddress((void**)&gwvt, g_wvt);
    cudaGetSymbolAddress((void**)&gwot, g_wot);
    cudaGetSymbolAddress((void**)&gq, g_q);
    cudaGetSymbolAddress((void**)&gk, g_k);
    cudaGetSymbolAddress((void**)&gvt, g_vt);
    cudaGetSymbolAddress((void**)&gctx, g_ctx);

    const int M = BB * LL;   // 4096

    // prep
    {
        const int nx = M * DD;
        cvt_h_kernel<<<nx / 1024, 256>>>(x, gxh, nx);
        dim3 blk(32, 8);
        transpose_h_kernel<<<dim3((NHQ * HD) / 32, DD / 32), blk>>>(Wq, gwqt, DD, NHQ * HD);
        transpose_h_kernel<<<dim3((NHKV * HD) / 32, DD / 32), blk>>>(Wk, gwkt, DD, NHKV * HD);
        transpose_h_kernel<<<dim3((NHKV * HD) / 32, DD / 32), blk>>>(Wv, gwvt, DD, NHKV * HD);
        transpose_h_kernel<<<dim3(DD / 32, (NHQ * HD) / 32), blk>>>(Wo, gwot, NHQ * HD, DD);
    }

    cudaFuncSetAttribute(gemm_f16, cudaFuncAttributeMaxDynamicSharedMemorySize, GSMEM);
    cudaFuncSetAttribute(attn_f16, cudaFuncAttributeMaxDynamicSharedMemorySize, ATT_SMEM);

    // fused QKV projections
    gemm_f16<<<768, 256, GSMEM>>>(gxh, gwqt, gwkt, gwvt, bq, bk, bv,
                                  gq, gk, gvt, out, 1);

    // attention
    {
        dim3 grid(LL / 128, NHQ, BB);
        attn_f16<<<grid, 256, ATT_SMEM>>>(gq, gk, gvt, gctx);
    }

    // O projection (fp32 out)
    gemm_f16<<<512, 256, GSMEM>>>(gctx, gwot, gwot, gwot, bo, bo, bo,
                                  gq, gk, gvt, out, 0);
}

// round 8
// speedup vs baseline: 7.9711x; 1.0472x over previous
#include <cuda_runtime.h>
#include <cuda_fp16.h>
#include <cstdint>
#include <math.h>

// Problem constants
#define BB   2
#define LL   2048
#define DD   2048
#define NHQ  32
#define NHKV 8
#define HD   64
#define GRP  4

// ---------------------------------------------------------------------------
// Scratch (allocation-free rule: __device__ globals)
// ---------------------------------------------------------------------------
__device__ __half g_xh[BB * LL * DD];              // x fp16
__device__ __half g_wqt[NHQ * HD * DD];            // Wq^T [N][K]
__device__ __half g_wkt[NHKV * HD * DD];
__device__ __half g_wvt[NHKV * HD * DD];
__device__ __half g_wot[DD * NHQ * HD];
__device__ __half g_q[BB * LL * NHQ * HD];         // q fp16 (pre-scaled by 0.125)
__device__ __half g_k[BB * LL * NHKV * HD];        // k fp16
__device__ __half g_vt[BB * NHKV * HD * LL];       // v fp16, [b][hk][d][L]
__device__ __half g_ctx[BB * LL * NHQ * HD];       // attention output fp16

// ---------------------------------------------------------------------------
// helpers
// ---------------------------------------------------------------------------
__device__ __forceinline__ void mma_f16(float* d, const uint32_t* a, const uint32_t* b) {
    asm volatile(
        "mma.sync.aligned.m16n8k16.row.col.f32.f16.f16.f32 "
        "{%0,%1,%2,%3}, {%4,%5,%6,%7}, {%8,%9}, {%0,%1,%2,%3};"
        : "+f"(d[0]), "+f"(d[1]), "+f"(d[2]), "+f"(d[3])
        : "r"(a[0]), "r"(a[1]), "r"(a[2]), "r"(a[3]), "r"(b[0]), "r"(b[1]));
}

// pack two f32 into one f16x2 register (lo = a, hi = b)
__device__ __forceinline__ uint32_t pack_h2(float a, float b) {
    uint32_t r;
    asm("cvt.rn.f16x2.f32 %0, %1, %2;" : "=r"(r) : "f"(b), "f"(a));
    return r;
}

// ldmatrix x4: 4 8x8 fp16 tiles
__device__ __forceinline__ void ldsm_x4(uint32_t& r0, uint32_t& r1, uint32_t& r2,
                                        uint32_t& r3, uint32_t addr) {
    asm volatile("ldmatrix.sync.aligned.m8n8.x4.shared.b16 {%0,%1,%2,%3}, [%4];"
                 : "=r"(r0), "=r"(r1), "=r"(r2), "=r"(r3) : "r"(addr));
}

__device__ __forceinline__ void cpasync16(uint32_t saddr, const void* g) {
    asm volatile("cp.async.cg.shared.global [%0], [%1], 16;\n" :: "r"(saddr), "l"(g) : "memory");
}
__device__ __forceinline__ void cp_commit() {
    asm volatile("cp.async.commit_group;\n" ::: "memory");
}
template <int N>
__device__ __forceinline__ void cp_wait() {
    asm volatile("cp.async.wait_group %0;\n" :: "n"(N) : "memory");
}

// ---------------------------------------------------------------------------
// prep: x -> fp16
// ---------------------------------------------------------------------------
__global__ __launch_bounds__(256) void cvt_h_kernel(
    const float* __restrict__ in, __half* __restrict__ out, int n)
{
    const int i = (blockIdx.x * 256 + threadIdx.x) * 4;
    if (i < n) {
        float4 v = *(const float4*)(in + i);
        uint32_t h0 = pack_h2(v.x, v.y);
        uint32_t h1 = pack_h2(v.z, v.w);
        *(uint32_t*)(out + i) = h0;
        *(uint32_t*)(out + i + 2) = h1;
    }
}

// ---------------------------------------------------------------------------
// prep: transpose W[K,N] -> WT[N,K] fp16
// ---------------------------------------------------------------------------
__global__ __launch_bounds__(256) void transpose_h_kernel(
    const float* __restrict__ W, __half* __restrict__ T, int K, int N)
{
    __shared__ float t[32][33];
    const int n0 = blockIdx.x * 32;
    const int k0 = blockIdx.y * 32;
    const int tx = threadIdx.x, ty = threadIdx.y;
#pragma unroll
    for (int i = 0; i < 4; i++)
        t[ty + i * 8][tx] = W[(long)(k0 + ty + i * 8) * N + n0 + tx];
    __syncthreads();
#pragma unroll
    for (int i = 0; i < 4; i++)
        T[(long)(n0 + ty + i * 8) * K + k0 + tx] = __float2half(t[tx][ty + i * 8]);
}

// ---------------------------------------------------------------------------
// fp16 tensor-core GEMM: C[M,N] = A[M,K] @ BT[N,K]^T + bias
// 128x128 tile, K-chunk 32, 3-stage cp.async, 256 threads, warp tile 64x32.
// ---------------------------------------------------------------------------
#define GSTR    20                 // 32-bit words per row (16 data + 4 pad)
#define GTILE_W (128 * GSTR)       // 2560 words per operand tile
#define GSTAGE_W (2 * GTILE_W)     // 5120 words = 20 KB
#define GSMEM   (3 * GSTAGE_W * 4) // 61440 B

__global__ __launch_bounds__(256, 2) void gemm_f16(
    const __half* __restrict__ A,
    const __half* __restrict__ Bq, const __half* __restrict__ Bk,
    const __half* __restrict__ Bv,
    const float* __restrict__ bias_q, const float* __restrict__ bias_k,
    const float* __restrict__ bias_v,
    __half* __restrict__ outq, __half* __restrict__ outk,
    __half* __restrict__ outvt, float* __restrict__ outf,
    int qkv_mode)
{
    extern __shared__ uint32_t smw[];
    const uint32_t smb = (uint32_t)__cvta_generic_to_shared(smw);

    int mode, bm, bn;
    if (qkv_mode) {
        const int bx = blockIdx.x;
        if (bx < 512)      { mode = 0; bn = (bx & 15) * 128; bm = (bx >> 4) * 128; }
        else if (bx < 640) { const int t = bx - 512; mode = 1; bn = (t & 3) * 128; bm = (t >> 2) * 128; }
        else               { const int t = bx - 640; mode = 2; bn = (t & 3) * 128; bm = (t >> 2) * 128; }
    } else { mode = 3; bn = (blockIdx.x & 15) * 128; bm = (blockIdx.x >> 4) * 128; }

    const __half* Bm = (mode == 1) ? Bk : (mode == 2) ? Bv : Bq;
    const float* bias = (mode == 1) ? bias_k : (mode == 2) ? bias_v : bias_q;

    const int tid = threadIdx.x;
    const int warp = tid >> 5;
    const int lane = tid & 31;
    const int gid = lane >> 2;
    const int tig = lane & 3;
    const int warp_m = warp >> 2;
    const int warp_n = warp & 3;
    const int r8 = lane & 7;
    const int qd = lane >> 3;       // ldmatrix quadrant

    const int l_row = tid >> 2;
    const int l_cc = tid & 3;

    auto load_stage = [&](int s, int kc) {
        const uint32_t base = smb + (uint32_t)(s * GSTAGE_W) * 4u;
#pragma unroll
        for (int j = 0; j < 2; j++) {
            const int row = l_row + 64 * j;
            cpasync16(base + (row * GSTR + l_cc * 4) * 4,
                      A + (long)(bm + row) * DD + kc + l_cc * 8);
            cpasync16(base + (GTILE_W + row * GSTR + l_cc * 4) * 4,
                      Bm + (long)(bn + row) * DD + kc + l_cc * 8);
        }
        cp_commit();
    };

    float acc[4][4][4];
#pragma unroll
    for (int i = 0; i < 4; i++)
#pragma unroll
        for (int j = 0; j < 4; j++)
#pragma unroll
            for (int r = 0; r < 4; r++) acc[i][j][r] = 0.0f;

    const int a_row_l = warp_m * 64 + (qd & 1) * 8 + r8;
    const int a_col_l = (qd >> 1) * 4;
    const int b_row_l = warp_n * 32 + (qd >> 1) * 8 + r8;
    const int b_col_l = (qd & 1) * 4;

    const int nk = DD / 32;   // 64
    load_stage(0, 0);
    load_stage(1, 32);

#pragma unroll 1
    for (int i = 0; i < nk; ++i) {
        const int s = i % 3;
        if (i + 1 < nk) cp_wait<1>(); else cp_wait<0>();
        __syncthreads();
        if (i + 2 < nk) load_stage((i + 2) % 3, (i + 2) * 32);

        const uint32_t abase = smb + (uint32_t)(s * GSTAGE_W) * 4u;
        const uint32_t bbase = abase + (uint32_t)GTILE_W * 4u;

#pragma unroll
        for (int ks = 0; ks < 2; ks++) {
            uint32_t af[4][4], bf[4][2];
#pragma unroll
            for (int mt = 0; mt < 4; mt++)
                ldsm_x4(af[mt][0], af[mt][1], af[mt][2], af[mt][3],
                        abase + ((a_row_l + mt * 16) * GSTR + ks * 8 + a_col_l) * 4);
#pragma unroll
            for (int p = 0; p < 4; p += 2)
                ldsm_x4(bf[p][0], bf[p][1], bf[p + 1][0], bf[p + 1][1],
                        bbase + ((b_row_l + p * 8) * GSTR + ks * 8 + b_col_l) * 4);
#pragma unroll
            for (int mt = 0; mt < 4; mt++)
#pragma unroll
                for (int nt = 0; nt < 4; nt++)
                    mma_f16(acc[mt][nt], af[mt], bf[nt]);
        }
    }

    // epilogue
#pragma unroll
    for (int mt = 0; mt < 4; mt++) {
        const int r = bm + warp_m * 64 + mt * 16 + gid;
#pragma unroll
        for (int nt = 0; nt < 4; nt++) {
            const int c = bn + warp_n * 32 + nt * 8 + 2 * tig;
            const float bx0 = bias[c], bx1 = bias[c + 1];
            float v00 = acc[mt][nt][0] + bx0, v01 = acc[mt][nt][1] + bx1;
            float v10 = acc[mt][nt][2] + bx0, v11 = acc[mt][nt][3] + bx1;
            if (mode == 0) {          // Q: scale by 1/8, fp16
                *(uint32_t*)(outq + (long)r * 2048 + c) =
                    pack_h2(v00 * 0.125f, v01 * 0.125f);
                *(uint32_t*)(outq + (long)(r + 8) * 2048 + c) =
                    pack_h2(v10 * 0.125f, v11 * 0.125f);
            } else if (mode == 1) {   // K: fp16
                *(uint32_t*)(outk + (long)r * 512 + c) = pack_h2(v00, v01);
                *(uint32_t*)(outk + (long)(r + 8) * 512 + c) = pack_h2(v10, v11);
            } else if (mode == 2) {   // V: fp16 transposed [b][hk][d][L]
                const int hk = c >> 6, d = c & 63;
                const int bb = r >> 11, lrow = r & 2047;
                const long base = ((long)(bb * NHKV + hk) * HD + d) * LL + lrow;
                outvt[base] = __float2half(v00);
                outvt[base + LL] = __float2half(v01);
                outvt[base + 8] = __float2half(v10);
                outvt[base + LL + 8] = __float2half(v11);
            } else {                  // O: fp32 out
                *(float2*)(outf + (long)r * 2048 + c) = make_float2(v00, v01);
                *(float2*)(outf + (long)(r + 8) * 2048 + c) = make_float2(v10, v11);
            }
        }
    }
}

// ---------------------------------------------------------------------------
// fp16 tensor-core flash attention.
// P kept entirely in registers: S C-fragment == P A-fragment layout.
// Block: 128 q rows x head x batch. 256 threads (8 warps), warp = 16 q rows.
// ---------------------------------------------------------------------------
#define ASTR 36                         // words per row (32 data + 4 pad)
#define KT_W (64 * ASTR)                // 2304 words per K/V buffer
#define ATT_SMEM (4 * KT_W * 4)         // 36864 B (no P buffer)
#define NKT (LL / 64)

__global__ __launch_bounds__(256, 2) void attn_f16(
    const __half* __restrict__ q, const __half* __restrict__ k,
    const __half* __restrict__ vt, __half* __restrict__ ctx)
{
    extern __shared__ uint32_t smw[];
    uint32_t* KsW = smw;                 // 2 x [64][36]
    uint32_t* VsW = smw + 2 * KT_W;      // 2 x [64][36]
    const uint32_t ks_s = (uint32_t)__cvta_generic_to_shared(KsW);
    const uint32_t vs_s = (uint32_t)__cvta_generic_to_shared(VsW);

    const int tid = threadIdx.x;
    const int warp = tid >> 5;
    const int lane = tid & 31;
    const int gid = lane >> 2;
    const int tig = lane & 3;
    const int r8 = lane & 7;
    const int qd = lane >> 3;
    const int qt = blockIdx.x;
    const int h  = blockIdx.y;
    const int b  = blockIdx.z;
    const int hk = h >> 2;
    const int qbase = qt * 128;

    // ldmatrix row/col components for B-type (K/V) pair loads
    const int bt_row = (qd >> 1) * 8 + r8;
    const int bt_col = (qd & 1) * 4;

    // Q fragments (fp16, pre-scaled). 4 k16-steps over HD=64.
    uint32_t qf[4][4];
    {
        const __half* qp = q + (long)(b * LL + qbase + warp * 16 + gid) * (NHQ * HD) + h * HD;
        const __half* qp8 = qp + (long)8 * (NHQ * HD);
#pragma unroll
        for (int ks = 0; ks < 4; ks++) {
            const int c = ks * 16 + 2 * tig;
            qf[ks][0] = *(const uint32_t*)(qp + c);
            qf[ks][1] = *(const uint32_t*)(qp8 + c);
            qf[ks][2] = *(const uint32_t*)(qp + c + 8);
            qf[ks][3] = *(const uint32_t*)(qp8 + c + 8);
        }
    }

    float o[8][4];
    float m[2], l[2];
#pragma unroll
    for (int nt = 0; nt < 8; nt++)
#pragma unroll
        for (int r = 0; r < 4; r++) o[nt][r] = 0.0f;
    m[0] = m[1] = -1e30f;
    l[0] = l[1] = 0.0f;

    const __half* kbase = k + (long)(b * LL) * (NHKV * HD) + hk * HD;
    const __half* vbase = vt + (long)(b * NHKV + hk) * HD * LL;

    auto load_kv = [&](int buf, int kt) {
#pragma unroll
        for (int j = 0; j < 2; j++) {
            const int c = tid + 256 * j;
            const int row = c >> 3;
            const int cc = c & 7;
            cpasync16(ks_s + ((buf * KT_W) + row * ASTR + cc * 4) * 4,
                      kbase + (long)(kt * 64 + row) * (NHKV * HD) + cc * 8);
            cpasync16(vs_s + ((buf * KT_W) + row * ASTR + cc * 4) * 4,
                      vbase + (long)row * LL + kt * 64 + cc * 8);
        }
        cp_commit();
    };

    load_kv(0, 0);

#pragma unroll 1
    for (int kt = 0; kt < NKT; kt++) {
        const int buf = kt & 1;
        if (kt + 1 < NKT) { load_kv(buf ^ 1, kt + 1); cp_wait<1>(); }
        else cp_wait<0>();
        __syncthreads();

        const uint32_t kb = ks_s + (uint32_t)(buf * KT_W) * 4u;
        const uint32_t vb = vs_s + (uint32_t)(buf * KT_W) * 4u;

        // ---- S = Q @ K^T ----
        float sacc[8][4];
#pragma unroll
        for (int nt = 0; nt < 8; nt++)
#pragma unroll
            for (int r = 0; r < 4; r++) sacc[nt][r] = 0.0f;

#pragma unroll
        for (int ks = 0; ks < 4; ks++) {
            uint32_t bf[8][2];
#pragma unroll
            for (int p = 0; p < 8; p += 2)
                ldsm_x4(bf[p][0], bf[p][1], bf[p + 1][0], bf[p + 1][1],
                        kb + ((p * 8 + bt_row) * ASTR + ks * 8 + bt_col) * 4);
#pragma unroll
            for (int nt = 0; nt < 8; nt++)
                mma_f16(sacc[nt], qf[ks], bf[nt]);
        }

        // ---- online softmax; P packed straight into A-fragment registers ----
        uint32_t ph[8][2];
#pragma unroll
        for (int i = 0; i < 2; i++) {
            const int r0 = 2 * i;
            float tm = -1e30f;
#pragma unroll
            for (int nt = 0; nt < 8; nt++)
                tm = fmaxf(tm, fmaxf(sacc[nt][r0], sacc[nt][r0 + 1]));
            tm = fmaxf(tm, __shfl_xor_sync(0xffffffffu, tm, 1));
            tm = fmaxf(tm, __shfl_xor_sync(0xffffffffu, tm, 2));
            const float mn = fmaxf(m[i], tm);
            const float alpha = __expf(m[i] - mn);
            m[i] = mn;
            float rs = 0.0f;
#pragma unroll
            for (int nt = 0; nt < 8; nt++) {
                float p0 = __expf(sacc[nt][r0] - mn);
                float p1 = __expf(sacc[nt][r0 + 1] - mn);
                rs += p0 + p1;
                ph[nt][i] = pack_h2(p0, p1);
            }
            rs += __shfl_xor_sync(0xffffffffu, rs, 1);
            rs += __shfl_xor_sync(0xffffffffu, rs, 2);
            l[i] = l[i] * alpha + rs;
#pragma unroll
            for (int nt = 0; nt < 8; nt++) {
                o[nt][r0]     *= alpha;
                o[nt][r0 + 1] *= alpha;
            }
        }

        // ---- O += P @ V (P register-resident) ----
#pragma unroll
        for (int ks = 0; ks < 4; ks++) {
            uint32_t vf[8][2];
            uint32_t pf[4] = { ph[2 * ks][0], ph[2 * ks][1],
                               ph[2 * ks + 1][0], ph[2 * ks + 1][1] };
#pragma unroll
            for (int p = 0; p < 8; p += 2)
                ldsm_x4(vf[p][0], vf[p][1], vf[p + 1][0], vf[p + 1][1],
                        vb + ((p * 8 + bt_row) * ASTR + ks * 8 + bt_col) * 4);
#pragma unroll
            for (int nt = 0; nt < 8; nt++)
                mma_f16(o[nt], pf, vf[nt]);
        }
        __syncthreads();
    }

    // ---- normalize + fp16 store ----
    {
        const float inv0 = 1.0f / l[0];
        const float inv1 = 1.0f / l[1];
        __half* cp0 = ctx + (long)(b * LL + qbase + warp * 16 + gid) * (NHQ * HD) + h * HD;
        __half* cp1 = cp0 + (long)8 * (NHQ * HD);
#pragma unroll
        for (int nt = 0; nt < 8; nt++) {
            const int c0 = nt * 8 + 2 * tig;
            *(uint32_t*)(cp0 + c0) = pack_h2(o[nt][0] * inv0, o[nt][1] * inv0);
            *(uint32_t*)(cp1 + c0) = pack_h2(o[nt][2] * inv1, o[nt][3] * inv1);
        }
    }
}

// ---------------------------------------------------------------------------
extern "C" void kernel_launch(void* const* d_in, const int* in_sizes, int n_in,
                              void* d_out, int out_size)
{
    const float* x  = (const float*)d_in[0];
    const float* Wq = (const float*)d_in[1];
    const float* bq = (const float*)d_in[2];
    const float* Wk = (const float*)d_in[3];
    const float* bk = (const float*)d_in[4];
    const float* Wv = (const float*)d_in[5];
    const float* bv = (const float*)d_in[6];
    const float* Wo = (const float*)d_in[7];
    const float* bo = (const float*)d_in[8];
    float* out = (float*)d_out;

    __half *gxh, *gwqt, *gwkt, *gwvt, *gwot, *gq, *gk, *gvt, *gctx;
    cudaGetSymbolAddress((void**)&gxh, g_xh);
    cudaGetSymbolAddress((void**)&gwqt, g_wqt);
    cudaGetSymbolAddress((void**)&gwkt, g_wkt);
    cudaGetSymbolAddress((void**)&gwvt, g_wvt);
    cudaGetSymbolAddress((void**)&gwot, g_wot);
    cudaGetSymbolAddress((void**)&gq, g_q);
    cudaGetSymbolAddress((void**)&gk, g_k);
    cudaGetSymbolAddress((void**)&gvt, g_vt);
    cudaGetSymbolAddress((void**)&gctx, g_ctx);

    const int M = BB * LL;   // 4096

    // prep
    {
        const int nx = M * DD;
        cvt_h_kernel<<<nx / 1024, 256>>>(x, gxh, nx);
        dim3 blk(32, 8);
        transpose_h_kernel<<<dim3((NHQ * HD) / 32, DD / 32), blk>>>(Wq, gwqt, DD, NHQ * HD);
        transpose_h_kernel<<<dim3((NHKV * HD) / 32, DD / 32), blk>>>(Wk, gwkt, DD, NHKV * HD);
        transpose_h_kernel<<<dim3((NHKV * HD) / 32, DD / 32), blk>>>(Wv, gwvt, DD, NHKV * HD);
        transpose_h_kernel<<<dim3(DD / 32, (NHQ * HD) / 32), blk>>>(Wo, gwot, NHQ * HD, DD);
    }

    cudaFuncSetAttribute(gemm_f16, cudaFuncAttributeMaxDynamicSharedMemorySize, GSMEM);
    cudaFuncSetAttribute(attn_f16, cudaFuncAttributeMaxDynamicSharedMemorySize, ATT_SMEM);

    // fused QKV projections
    gemm_f16<<<768, 256, GSMEM>>>(gxh, gwqt, gwkt, gwvt, bq, bk, bv,
                                  gq, gk, gvt, out, 1);

    // attention
    {
        dim3 grid(LL / 128, NHQ, BB);
        attn_f16<<<grid, 256, ATT_SMEM>>>(gq, gk, gvt, gctx);
    }

    // O projection (fp32 out)
    gemm_f16<<<512, 256, GSMEM>>>(gctx, gwot, gwot, gwot, bo, bo, bo,
                                  gq, gk, gvt, out, 0);
}

// round 9
// speedup vs baseline: 8.5485x; 1.0724x over previous
#include <cuda_runtime.h>
#include <cuda_fp16.h>
#include <cstdint>
#include <math.h>

// Problem constants
#define BB   2
#define LL   2048
#define DD   2048
#define NHQ  32
#define NHKV 8
#define HD   64
#define GRP  4

// ---------------------------------------------------------------------------
// Scratch (allocation-free rule: __device__ globals)
// ---------------------------------------------------------------------------
__device__ __half g_xh[BB * LL * DD];              // x fp16
__device__ __half g_wqt[NHQ * HD * DD];            // Wq^T [N][K]
__device__ __half g_wkt[NHKV * HD * DD];
__device__ __half g_wvt[NHKV * HD * DD];
__device__ __half g_wot[DD * NHQ * HD];
__device__ __half g_q[BB * LL * NHQ * HD];         // q fp16 (pre-scaled by log2e/8)
__device__ __half g_k[BB * LL * NHKV * HD];        // k fp16
__device__ __half g_vt[BB * NHKV * HD * LL];       // v fp16, [b][hk][d][L]
__device__ __half g_ctx[BB * LL * NHQ * HD];       // attention output fp16

// ---------------------------------------------------------------------------
// helpers
// ---------------------------------------------------------------------------
__device__ __forceinline__ void mma_f16(float* d, const uint32_t* a, const uint32_t* b) {
    asm volatile(
        "mma.sync.aligned.m16n8k16.row.col.f32.f16.f16.f32 "
        "{%0,%1,%2,%3}, {%4,%5,%6,%7}, {%8,%9}, {%0,%1,%2,%3};"
        : "+f"(d[0]), "+f"(d[1]), "+f"(d[2]), "+f"(d[3])
        : "r"(a[0]), "r"(a[1]), "r"(a[2]), "r"(a[3]), "r"(b[0]), "r"(b[1]));
}

// pack two f32 into one f16x2 register (lo = a, hi = b)
__device__ __forceinline__ uint32_t pack_h2(float a, float b) {
    uint32_t r;
    asm("cvt.rn.f16x2.f32 %0, %1, %2;" : "=r"(r) : "f"(b), "f"(a));
    return r;
}

// ldmatrix x4: 4 8x8 fp16 tiles
__device__ __forceinline__ void ldsm_x4(uint32_t& r0, uint32_t& r1, uint32_t& r2,
                                        uint32_t& r3, uint32_t addr) {
    asm volatile("ldmatrix.sync.aligned.m8n8.x4.shared.b16 {%0,%1,%2,%3}, [%4];"
                 : "=r"(r0), "=r"(r1), "=r"(r2), "=r"(r3) : "r"(addr));
}

__device__ __forceinline__ void cpasync16(uint32_t saddr, const void* g) {
    asm volatile("cp.async.cg.shared.global [%0], [%1], 16;\n" :: "r"(saddr), "l"(g) : "memory");
}
__device__ __forceinline__ void cp_commit() {
    asm volatile("cp.async.commit_group;\n" ::: "memory");
}
template <int N>
__device__ __forceinline__ void cp_wait() {
    asm volatile("cp.async.wait_group %0;\n" :: "n"(N) : "memory");
}

// ---------------------------------------------------------------------------
// prep: x -> fp16
// ---------------------------------------------------------------------------
__global__ __launch_bounds__(256) void cvt_h_kernel(
    const float* __restrict__ in, __half* __restrict__ out, int n)
{
    const int i = (blockIdx.x * 256 + threadIdx.x) * 4;
    if (i < n) {
        float4 v = *(const float4*)(in + i);
        uint32_t h0 = pack_h2(v.x, v.y);
        uint32_t h1 = pack_h2(v.z, v.w);
        *(uint32_t*)(out + i) = h0;
        *(uint32_t*)(out + i + 2) = h1;
    }
}

// ---------------------------------------------------------------------------
// prep: transpose W[K,N] -> WT[N,K] fp16
// ---------------------------------------------------------------------------
__global__ __launch_bounds__(256) void transpose_h_kernel(
    const float* __restrict__ W, __half* __restrict__ T, int K, int N)
{
    __shared__ float t[32][33];
    const int n0 = blockIdx.x * 32;
    const int k0 = blockIdx.y * 32;
    const int tx = threadIdx.x, ty = threadIdx.y;
#pragma unroll
    for (int i = 0; i < 4; i++)
        t[ty + i * 8][tx] = W[(long)(k0 + ty + i * 8) * N + n0 + tx];
    __syncthreads();
#pragma unroll
    for (int i = 0; i < 4; i++)
        T[(long)(n0 + ty + i * 8) * K + k0 + tx] = __float2half(t[tx][ty + i * 8]);
}

// ---------------------------------------------------------------------------
// fp16 tensor-core GEMM: C[M,N] = A[M,K] @ BT[N,K]^T + bias
// 128x128 tile, K-chunk 64, 3-stage cp.async, 256 threads, warp tile 64x32.
// ---------------------------------------------------------------------------
#define GSTR    36                 // 32-bit words per row (32 data + 4 pad)
#define GTILE_W (128 * GSTR)       // 4608 words per operand tile
#define GSTAGE_W (2 * GTILE_W)     // 9216 words = 36 KB
#define GSMEM   (3 * GSTAGE_W * 4) // 110592 B

#define QSCALE 0.1803368867f       // 0.125 * log2(e)

__global__ __launch_bounds__(256, 2) void gemm_f16(
    const __half* __restrict__ A,
    const __half* __restrict__ Bq, const __half* __restrict__ Bk,
    const __half* __restrict__ Bv,
    const float* __restrict__ bias_q, const float* __restrict__ bias_k,
    const float* __restrict__ bias_v,
    __half* __restrict__ outq, __half* __restrict__ outk,
    __half* __restrict__ outvt, float* __restrict__ outf,
    int qkv_mode)
{
    extern __shared__ uint32_t smw[];
    const uint32_t smb = (uint32_t)__cvta_generic_to_shared(smw);

    int mode, bm, bn;
    if (qkv_mode) {
        const int bx = blockIdx.x;
        if (bx < 512)      { mode = 0; bn = (bx & 15) * 128; bm = (bx >> 4) * 128; }
        else if (bx < 640) { const int t = bx - 512; mode = 1; bn = (t & 3) * 128; bm = (t >> 2) * 128; }
        else               { const int t = bx - 640; mode = 2; bn = (t & 3) * 128; bm = (t >> 2) * 128; }
    } else { mode = 3; bn = (blockIdx.x & 15) * 128; bm = (blockIdx.x >> 4) * 128; }

    const __half* Bm = (mode == 1) ? Bk : (mode == 2) ? Bv : Bq;
    const float* bias = (mode == 1) ? bias_k : (mode == 2) ? bias_v : bias_q;

    const int tid = threadIdx.x;
    const int warp = tid >> 5;
    const int lane = tid & 31;
    const int gid = lane >> 2;
    const int tig = lane & 3;
    const int warp_m = warp >> 2;
    const int warp_n = warp & 3;
    const int r8 = lane & 7;
    const int qd = lane >> 3;       // ldmatrix quadrant

    auto load_stage = [&](int s, int kc) {
        const uint32_t base = smb + (uint32_t)(s * GSTAGE_W) * 4u;
#pragma unroll
        for (int j = 0; j < 4; j++) {
            const int c = tid + 256 * j;       // 0..1023
            const int row = c >> 3;
            const int cc = c & 7;
            cpasync16(base + (row * GSTR + cc * 4) * 4,
                      A + (long)(bm + row) * DD + kc + cc * 8);
            cpasync16(base + (GTILE_W + row * GSTR + cc * 4) * 4,
                      Bm + (long)(bn + row) * DD + kc + cc * 8);
        }
        cp_commit();
    };

    float acc[4][4][4];
#pragma unroll
    for (int i = 0; i < 4; i++)
#pragma unroll
        for (int j = 0; j < 4; j++)
#pragma unroll
            for (int r = 0; r < 4; r++) acc[i][j][r] = 0.0f;

    const int a_row_l = warp_m * 64 + (qd & 1) * 8 + r8;
    const int a_col_l = (qd >> 1) * 4;
    const int b_row_l = warp_n * 32 + (qd >> 1) * 8 + r8;
    const int b_col_l = (qd & 1) * 4;

    const int nk = DD / 64;   // 32
    load_stage(0, 0);
    load_stage(1, 64);

#pragma unroll 1
    for (int i = 0; i < nk; ++i) {
        const int s = i % 3;
        if (i + 1 < nk) cp_wait<1>(); else cp_wait<0>();
        __syncthreads();
        if (i + 2 < nk) load_stage((i + 2) % 3, (i + 2) * 64);

        const uint32_t abase = smb + (uint32_t)(s * GSTAGE_W) * 4u;
        const uint32_t bbase = abase + (uint32_t)GTILE_W * 4u;

#pragma unroll
        for (int ks = 0; ks < 4; ks++) {
            uint32_t af[4][4], bf[4][2];
#pragma unroll
            for (int mt = 0; mt < 4; mt++)
                ldsm_x4(af[mt][0], af[mt][1], af[mt][2], af[mt][3],
                        abase + ((a_row_l + mt * 16) * GSTR + ks * 8 + a_col_l) * 4);
#pragma unroll
            for (int p = 0; p < 4; p += 2)
                ldsm_x4(bf[p][0], bf[p][1], bf[p + 1][0], bf[p + 1][1],
                        bbase + ((b_row_l + p * 8) * GSTR + ks * 8 + b_col_l) * 4);
#pragma unroll
            for (int mt = 0; mt < 4; mt++)
#pragma unroll
                for (int nt = 0; nt < 4; nt++)
                    mma_f16(acc[mt][nt], af[mt], bf[nt]);
        }
    }

    // epilogue
#pragma unroll
    for (int mt = 0; mt < 4; mt++) {
        const int r = bm + warp_m * 64 + mt * 16 + gid;
#pragma unroll
        for (int nt = 0; nt < 4; nt++) {
            const int c = bn + warp_n * 32 + nt * 8 + 2 * tig;
            const float bx0 = bias[c], bx1 = bias[c + 1];
            float v00 = acc[mt][nt][0] + bx0, v01 = acc[mt][nt][1] + bx1;
            float v10 = acc[mt][nt][2] + bx0, v11 = acc[mt][nt][3] + bx1;
            if (mode == 0) {          // Q: scale by log2e/8, fp16
                *(uint32_t*)(outq + (long)r * 2048 + c) =
                    pack_h2(v00 * QSCALE, v01 * QSCALE);
                *(uint32_t*)(outq + (long)(r + 8) * 2048 + c) =
                    pack_h2(v10 * QSCALE, v11 * QSCALE);
            } else if (mode == 1) {   // K: fp16
                *(uint32_t*)(outk + (long)r * 512 + c) = pack_h2(v00, v01);
                *(uint32_t*)(outk + (long)(r + 8) * 512 + c) = pack_h2(v10, v11);
            } else if (mode == 2) {   // V: fp16 transposed [b][hk][d][L]
                const int hk = c >> 6, d = c & 63;
                const int bb = r >> 11, lrow = r & 2047;
                const long base = ((long)(bb * NHKV + hk) * HD + d) * LL + lrow;
                outvt[base] = __float2half(v00);
                outvt[base + LL] = __float2half(v01);
                outvt[base + 8] = __float2half(v10);
                outvt[base + LL + 8] = __float2half(v11);
            } else {                  // O: fp32 out
                *(float2*)(outf + (long)r * 2048 + c) = make_float2(v00, v01);
                *(float2*)(outf + (long)(r + 8) * 2048 + c) = make_float2(v10, v11);
            }
        }
    }
}

// ---------------------------------------------------------------------------
// fp16 tensor-core flash attention (exp2-domain softmax, register P).
// Block: 128 q rows x head x batch. 256 threads (8 warps), warp = 16 q rows.
// One __syncthreads per K-tile.
// ---------------------------------------------------------------------------
#define ASTR 36                         // words per row (32 data + 4 pad)
#define KT_W (64 * ASTR)                // 2304 words per K/V buffer
#define ATT_SMEM (4 * KT_W * 4)         // 36864 B
#define NKT (LL / 64)

__global__ __launch_bounds__(256, 2) void attn_f16(
    const __half* __restrict__ q, const __half* __restrict__ k,
    const __half* __restrict__ vt, __half* __restrict__ ctx)
{
    extern __shared__ uint32_t smw[];
    uint32_t* KsW = smw;                 // 2 x [64][36]
    uint32_t* VsW = smw + 2 * KT_W;      // 2 x [64][36]
    const uint32_t ks_s = (uint32_t)__cvta_generic_to_shared(KsW);
    const uint32_t vs_s = (uint32_t)__cvta_generic_to_shared(VsW);

    const int tid = threadIdx.x;
    const int warp = tid >> 5;
    const int lane = tid & 31;
    const int gid = lane >> 2;
    const int tig = lane & 3;
    const int r8 = lane & 7;
    const int qd = lane >> 3;
    const int qt = blockIdx.x;
    const int h  = blockIdx.y;
    const int b  = blockIdx.z;
    const int hk = h >> 2;
    const int qbase = qt * 128;

    const int bt_row = (qd >> 1) * 8 + r8;
    const int bt_col = (qd & 1) * 4;

    // Q fragments (fp16, pre-scaled by log2e/8). 4 k16-steps over HD=64.
    uint32_t qf[4][4];
    {
        const __half* qp = q + (long)(b * LL + qbase + warp * 16 + gid) * (NHQ * HD) + h * HD;
        const __half* qp8 = qp + (long)8 * (NHQ * HD);
#pragma unroll
        for (int ks = 0; ks < 4; ks++) {
            const int c = ks * 16 + 2 * tig;
            qf[ks][0] = *(const uint32_t*)(qp + c);
            qf[ks][1] = *(const uint32_t*)(qp8 + c);
            qf[ks][2] = *(const uint32_t*)(qp + c + 8);
            qf[ks][3] = *(const uint32_t*)(qp8 + c + 8);
        }
    }

    float o[8][4];
    float m[2], l[2];
#pragma unroll
    for (int nt = 0; nt < 8; nt++)
#pragma unroll
        for (int r = 0; r < 4; r++) o[nt][r] = 0.0f;
    m[0] = m[1] = -1e30f;
    l[0] = l[1] = 0.0f;

    const __half* kbase = k + (long)(b * LL) * (NHKV * HD) + hk * HD;
    const __half* vbase = vt + (long)(b * NHKV + hk) * HD * LL;

    auto load_kv = [&](int buf, int kt) {
#pragma unroll
        for (int j = 0; j < 2; j++) {
            const int c = tid + 256 * j;
            const int row = c >> 3;
            const int cc = c & 7;
            cpasync16(ks_s + ((buf * KT_W) + row * ASTR + cc * 4) * 4,
                      kbase + (long)(kt * 64 + row) * (NHKV * HD) + cc * 8);
            cpasync16(vs_s + ((buf * KT_W) + row * ASTR + cc * 4) * 4,
                      vbase + (long)row * LL + kt * 64 + cc * 8);
        }
        cp_commit();
    };

    load_kv(0, 0);

#pragma unroll 1
    for (int kt = 0; kt < NKT; kt++) {
        const int buf = kt & 1;
        cp_wait<0>();
        __syncthreads();
        if (kt + 1 < NKT) load_kv(buf ^ 1, kt + 1);

        const uint32_t kb = ks_s + (uint32_t)(buf * KT_W) * 4u;
        const uint32_t vb = vs_s + (uint32_t)(buf * KT_W) * 4u;

        // ---- S = Q @ K^T (log2 domain) ----
        float sacc[8][4];
#pragma unroll
        for (int nt = 0; nt < 8; nt++)
#pragma unroll
            for (int r = 0; r < 4; r++) sacc[nt][r] = 0.0f;

#pragma unroll
        for (int ks = 0; ks < 4; ks++) {
            uint32_t bf[8][2];
#pragma unroll
            for (int p = 0; p < 8; p += 2)
                ldsm_x4(bf[p][0], bf[p][1], bf[p + 1][0], bf[p + 1][1],
                        kb + ((p * 8 + bt_row) * ASTR + ks * 8 + bt_col) * 4);
#pragma unroll
            for (int nt = 0; nt < 8; nt++)
                mma_f16(sacc[nt], qf[ks], bf[nt]);
        }

        // ---- online softmax (exp2); P packed into A-fragment registers ----
        uint32_t ph[8][2];
#pragma unroll
        for (int i = 0; i < 2; i++) {
            const int r0 = 2 * i;
            float tm = -1e30f;
#pragma unroll
            for (int nt = 0; nt < 8; nt++)
                tm = fmaxf(tm, fmaxf(sacc[nt][r0], sacc[nt][r0 + 1]));
            tm = fmaxf(tm, __shfl_xor_sync(0xffffffffu, tm, 1));
            tm = fmaxf(tm, __shfl_xor_sync(0xffffffffu, tm, 2));
            const float mn = fmaxf(m[i], tm);
            const float alpha = exp2f(m[i] - mn);
            m[i] = mn;
            float rs = 0.0f;
#pragma unroll
            for (int nt = 0; nt < 8; nt++) {
                float p0 = exp2f(sacc[nt][r0] - mn);
                float p1 = exp2f(sacc[nt][r0 + 1] - mn);
                rs += p0 + p1;
                ph[nt][i] = pack_h2(p0, p1);
            }
            rs += __shfl_xor_sync(0xffffffffu, rs, 1);
            rs += __shfl_xor_sync(0xffffffffu, rs, 2);
            l[i] = l[i] * alpha + rs;
#pragma unroll
            for (int nt = 0; nt < 8; nt++) {
                o[nt][r0]     *= alpha;
                o[nt][r0 + 1] *= alpha;
            }
        }

        // ---- O += P @ V (P register-resident) ----
#pragma unroll
        for (int ks = 0; ks < 4; ks++) {
            uint32_t vf[8][2];
            uint32_t pf[4] = { ph[2 * ks][0], ph[2 * ks][1],
                               ph[2 * ks + 1][0], ph[2 * ks + 1][1] };
#pragma unroll
            for (int p = 0; p < 8; p += 2)
                ldsm_x4(vf[p][0], vf[p][1], vf[p + 1][0], vf[p + 1][1],
                        vb + ((p * 8 + bt_row) * ASTR + ks * 8 + bt_col) * 4);
#pragma unroll
            for (int nt = 0; nt < 8; nt++)
                mma_f16(o[nt], pf, vf[nt]);
        }
    }

    // ---- normalize + fp16 store ----
    {
        const float inv0 = 1.0f / l[0];
        const float inv1 = 1.0f / l[1];
        __half* cp0 = ctx + (long)(b * LL + qbase + warp * 16 + gid) * (NHQ * HD) + h * HD;
        __half* cp1 = cp0 + (long)8 * (NHQ * HD);
#pragma unroll
        for (int nt = 0; nt < 8; nt++) {
            const int c0 = nt * 8 + 2 * tig;
            *(uint32_t*)(cp0 + c0) = pack_h2(o[nt][0] * inv0, o[nt][1] * inv0);
            *(uint32_t*)(cp1 + c0) = pack_h2(o[nt][2] * inv1, o[nt][3] * inv1);
        }
    }
}

// ---------------------------------------------------------------------------
extern "C" void kernel_launch(void* const* d_in, const int* in_sizes, int n_in,
                              void* d_out, int out_size)
{
    const float* x  = (const float*)d_in[0];
    const float* Wq = (const float*)d_in[1];
    const float* bq = (const float*)d_in[2];
    const float* Wk = (const float*)d_in[3];
    const float* bk = (const float*)d_in[4];
    const float* Wv = (const float*)d_in[5];
    const float* bv = (const float*)d_in[6];
    const float* Wo = (const float*)d_in[7];
    const float* bo = (const float*)d_in[8];
    float* out = (float*)d_out;

    __half *gxh, *gwqt, *gwkt, *gwvt, *gwot, *gq, *gk, *gvt, *gctx;
    cudaGetSymbolAddress((void**)&gxh, g_xh);
    cudaGetSymbolAddress((void**)&gwqt, g_wqt);
    cudaGetSymbolAddress((void**)&gwkt, g_wkt);
    cudaGetSymbolAddress((void**)&gwvt, g_wvt);
    cudaGetSymbolAddress((void**)&gwot, g_wot);
    cudaGetSymbolAddress((void**)&gq, g_q);
    cudaGetSymbolAddress((void**)&gk, g_k);
    cudaGetSymbolAddress((void**)&gvt, g_vt);
    cudaGetSymbolAddress((void**)&gctx, g_ctx);

    const int M = BB * LL;   // 4096

    // prep
    {
        const int nx = M * DD;
        cvt_h_kernel<<<nx / 1024, 256>>>(x, gxh, nx);
        dim3 blk(32, 8);
        transpose_h_kernel<<<dim3((NHQ * HD) / 32, DD / 32), blk>>>(Wq, gwqt, DD, NHQ * HD);
        transpose_h_kernel<<<dim3((NHKV * HD) / 32, DD / 32), blk>>>(Wk, gwkt, DD, NHKV * HD);
        transpose_h_kernel<<<dim3((NHKV * HD) / 32, DD / 32), blk>>>(Wv, gwvt, DD, NHKV * HD);
        transpose_h_kernel<<<dim3(DD / 32, (NHQ * HD) / 32), blk>>>(Wo, gwot, NHQ * HD, DD);
    }

    cudaFuncSetAttribute(gemm_f16, cudaFuncAttributeMaxDynamicSharedMemorySize, GSMEM);
    cudaFuncSetAttribute(attn_f16, cudaFuncAttributeMaxDynamicSharedMemorySize, ATT_SMEM);

    // fused QKV projections
    gemm_f16<<<768, 256, GSMEM>>>(gxh, gwqt, gwkt, gwvt, bq, bk, bv,
                                  gq, gk, gvt, out, 1);

    // attention
    {
        dim3 grid(LL / 128, NHQ, BB);
        attn_f16<<<grid, 256, ATT_SMEM>>>(gq, gk, gvt, gctx);
    }

    // O projection (fp32 out)
    gemm_f16<<<512, 256, GSMEM>>>(gctx, gwot, gwot, gwot, bo, bo, bo,
                                  gq, gk, gvt, out, 0);
}

// round 10
// speedup vs baseline: 8.7179x; 1.0198x over previous
#include <cuda_runtime.h>
#include <cuda_fp16.h>
#include <cstdint>
#include <math.h>

// Problem constants
#define BB   2
#define LL   2048
#define DD   2048
#define NHQ  32
#define NHKV 8
#define HD   64
#define GRP  4

// ---------------------------------------------------------------------------
// Scratch (allocation-free rule: __device__ globals)
// ---------------------------------------------------------------------------
__device__ __half g_xh[BB * LL * DD];              // x fp16
__device__ __half g_wqt[NHQ * HD * DD];            // Wq^T [N][K]
__device__ __half g_wkt[NHKV * HD * DD];
__device__ __half g_wvt[NHKV * HD * DD];
__device__ __half g_wot[DD * NHQ * HD];
__device__ __half g_q[BB * LL * NHQ * HD];         // q fp16 (pre-scaled by log2e/8)
__device__ __half g_k[BB * LL * NHKV * HD];        // k fp16
__device__ __half g_vt[BB * NHKV * HD * LL];       // v fp16, [b][hk][d][L]
__device__ __half g_ctx[BB * LL * NHQ * HD];       // attention output fp16

// ---------------------------------------------------------------------------
// helpers
// ---------------------------------------------------------------------------
__device__ __forceinline__ void mma_f16(float* d, const uint32_t* a, const uint32_t* b) {
    asm volatile(
        "mma.sync.aligned.m16n8k16.row.col.f32.f16.f16.f32 "
        "{%0,%1,%2,%3}, {%4,%5,%6,%7}, {%8,%9}, {%0,%1,%2,%3};"
        : "+f"(d[0]), "+f"(d[1]), "+f"(d[2]), "+f"(d[3])
        : "r"(a[0]), "r"(a[1]), "r"(a[2]), "r"(a[3]), "r"(b[0]), "r"(b[1]));
}

// pack two f32 into one f16x2 register (lo = a, hi = b)
__device__ __forceinline__ uint32_t pack_h2(float a, float b) {
    uint32_t r;
    asm("cvt.rn.f16x2.f32 %0, %1, %2;" : "=r"(r) : "f"(b), "f"(a));
    return r;
}

// explicit fast exp2 (MUFU.EX2), independent of --use_fast_math
__device__ __forceinline__ float ex2f(float x) {
    float y;
    asm("ex2.approx.f32 %0, %1;" : "=f"(y) : "f"(x));
    return y;
}

// ldmatrix x4: 4 8x8 fp16 tiles
__device__ __forceinline__ void ldsm_x4(uint32_t& r0, uint32_t& r1, uint32_t& r2,
                                        uint32_t& r3, uint32_t addr) {
    asm volatile("ldmatrix.sync.aligned.m8n8.x4.shared.b16 {%0,%1,%2,%3}, [%4];"
                 : "=r"(r0), "=r"(r1), "=r"(r2), "=r"(r3) : "r"(addr));
}

// ldmatrix x2: 2 8x8 fp16 tiles (addresses from lanes 0-15)
__device__ __forceinline__ void ldsm_x2(uint32_t& r0, uint32_t& r1, uint32_t addr) {
    asm volatile("ldmatrix.sync.aligned.m8n8.x2.shared.b16 {%0,%1}, [%2];"
                 : "=r"(r0), "=r"(r1) : "r"(addr));
}

__device__ __forceinline__ void cpasync16(uint32_t saddr, const void* g) {
    asm volatile("cp.async.cg.shared.global [%0], [%1], 16;\n" :: "r"(saddr), "l"(g) : "memory");
}
__device__ __forceinline__ void cp_commit() {
    asm volatile("cp.async.commit_group;\n" ::: "memory");
}
template <int N>
__device__ __forceinline__ void cp_wait() {
    asm volatile("cp.async.wait_group %0;\n" :: "n"(N) : "memory");
}

// ---------------------------------------------------------------------------
// prep: x -> fp16
// ---------------------------------------------------------------------------
__global__ __launch_bounds__(256) void cvt_h_kernel(
    const float* __restrict__ in, __half* __restrict__ out, int n)
{
    const int i = (blockIdx.x * 256 + threadIdx.x) * 4;
    if (i < n) {
        float4 v = *(const float4*)(in + i);
        uint32_t h0 = pack_h2(v.x, v.y);
        uint32_t h1 = pack_h2(v.z, v.w);
        *(uint32_t*)(out + i) = h0;
        *(uint32_t*)(out + i + 2) = h1;
    }
}

// ---------------------------------------------------------------------------
// prep: transpose W[K,N] -> WT[N,K] fp16
// ---------------------------------------------------------------------------
__global__ __launch_bounds__(256) void transpose_h_kernel(
    const float* __restrict__ W, __half* __restrict__ T, int K, int N)
{
    __shared__ float t[32][33];
    const int n0 = blockIdx.x * 32;
    const int k0 = blockIdx.y * 32;
    const int tx = threadIdx.x, ty = threadIdx.y;
#pragma unroll
    for (int i = 0; i < 4; i++)
        t[ty + i * 8][tx] = W[(long)(k0 + ty + i * 8) * N + n0 + tx];
    __syncthreads();
#pragma unroll
    for (int i = 0; i < 4; i++)
        T[(long)(n0 + ty + i * 8) * K + k0 + tx] = __float2half(t[tx][ty + i * 8]);
}

// ---------------------------------------------------------------------------
// fp16 tensor-core GEMM: C[M,N] = A[M,K] @ BT[N,K]^T + bias
// 128x128 tile, K-chunk 64, 3-stage cp.async, 256 threads, warp tile 64x32.
// ---------------------------------------------------------------------------
#define GSTR    36                 // 32-bit words per row (32 data + 4 pad)
#define GTILE_W (128 * GSTR)       // 4608 words per operand tile
#define GSTAGE_W (2 * GTILE_W)     // 9216 words = 36 KB
#define GSMEM   (3 * GSTAGE_W * 4) // 110592 B

#define QSCALE 0.1803368867f       // 0.125 * log2(e)

__global__ __launch_bounds__(256, 2) void gemm_f16(
    const __half* __restrict__ A,
    const __half* __restrict__ Bq, const __half* __restrict__ Bk,
    const __half* __restrict__ Bv,
    const float* __restrict__ bias_q, const float* __restrict__ bias_k,
    const float* __restrict__ bias_v,
    __half* __restrict__ outq, __half* __restrict__ outk,
    __half* __restrict__ outvt, float* __restrict__ outf,
    int qkv_mode)
{
    extern __shared__ uint32_t smw[];
    const uint32_t smb = (uint32_t)__cvta_generic_to_shared(smw);

    int mode, bm, bn;
    if (qkv_mode) {
        const int bx = blockIdx.x;
        if (bx < 512)      { mode = 0; bn = (bx & 15) * 128; bm = (bx >> 4) * 128; }
        else if (bx < 640) { const int t = bx - 512; mode = 1; bn = (t & 3) * 128; bm = (t >> 2) * 128; }
        else               { const int t = bx - 640; mode = 2; bn = (t & 3) * 128; bm = (t >> 2) * 128; }
    } else { mode = 3; bn = (blockIdx.x & 15) * 128; bm = (blockIdx.x >> 4) * 128; }

    const __half* Bm = (mode == 1) ? Bk : (mode == 2) ? Bv : Bq;
    const float* bias = (mode == 1) ? bias_k : (mode == 2) ? bias_v : bias_q;

    const int tid = threadIdx.x;
    const int warp = tid >> 5;
    const int lane = tid & 31;
    const int gid = lane >> 2;
    const int tig = lane & 3;
    const int warp_m = warp >> 2;
    const int warp_n = warp & 3;
    const int r8 = lane & 7;
    const int qd = lane >> 3;       // ldmatrix quadrant

    auto load_stage = [&](int s, int kc) {
        const uint32_t base = smb + (uint32_t)(s * GSTAGE_W) * 4u;
#pragma unroll
        for (int j = 0; j < 4; j++) {
            const int c = tid + 256 * j;       // 0..1023
            const int row = c >> 3;
            const int cc = c & 7;
            cpasync16(base + (row * GSTR + cc * 4) * 4,
                      A + (long)(bm + row) * DD + kc + cc * 8);
            cpasync16(base + (GTILE_W + row * GSTR + cc * 4) * 4,
                      Bm + (long)(bn + row) * DD + kc + cc * 8);
        }
        cp_commit();
    };

    float acc[4][4][4];
#pragma unroll
    for (int i = 0; i < 4; i++)
#pragma unroll
        for (int j = 0; j < 4; j++)
#pragma unroll
            for (int r = 0; r < 4; r++) acc[i][j][r] = 0.0f;

    const int a_row_l = warp_m * 64 + (qd & 1) * 8 + r8;
    const int a_col_l = (qd >> 1) * 4;
    const int b_row_l = warp_n * 32 + (qd >> 1) * 8 + r8;
    const int b_col_l = (qd & 1) * 4;

    const int nk = DD / 64;   // 32
    load_stage(0, 0);
    load_stage(1, 64);

#pragma unroll 1
    for (int i = 0; i < nk; ++i) {
        const int s = i % 3;
        if (i + 1 < nk) cp_wait<1>(); else cp_wait<0>();
        __syncthreads();
        if (i + 2 < nk) load_stage((i + 2) % 3, (i + 2) * 64);

        const uint32_t abase = smb + (uint32_t)(s * GSTAGE_W) * 4u;
        const uint32_t bbase = abase + (uint32_t)GTILE_W * 4u;

#pragma unroll
        for (int ks = 0; ks < 4; ks++) {
            uint32_t af[4][4], bf[4][2];
#pragma unroll
            for (int mt = 0; mt < 4; mt++)
                ldsm_x4(af[mt][0], af[mt][1], af[mt][2], af[mt][3],
                        abase + ((a_row_l + mt * 16) * GSTR + ks * 8 + a_col_l) * 4);
#pragma unroll
            for (int p = 0; p < 4; p += 2)
                ldsm_x4(bf[p][0], bf[p][1], bf[p + 1][0], bf[p + 1][1],
                        bbase + ((b_row_l + p * 8) * GSTR + ks * 8 + b_col_l) * 4);
#pragma unroll
            for (int mt = 0; mt < 4; mt++)
#pragma unroll
                for (int nt = 0; nt < 4; nt++)
                    mma_f16(acc[mt][nt], af[mt], bf[nt]);
        }
    }

    // epilogue
#pragma unroll
    for (int mt = 0; mt < 4; mt++) {
        const int r = bm + warp_m * 64 + mt * 16 + gid;
#pragma unroll
        for (int nt = 0; nt < 4; nt++) {
            const int c = bn + warp_n * 32 + nt * 8 + 2 * tig;
            const float bx0 = bias[c], bx1 = bias[c + 1];
            float v00 = acc[mt][nt][0] + bx0, v01 = acc[mt][nt][1] + bx1;
            float v10 = acc[mt][nt][2] + bx0, v11 = acc[mt][nt][3] + bx1;
            if (mode == 0) {          // Q: scale by log2e/8, fp16
                *(uint32_t*)(outq + (long)r * 2048 + c) =
                    pack_h2(v00 * QSCALE, v01 * QSCALE);
                *(uint32_t*)(outq + (long)(r + 8) * 2048 + c) =
                    pack_h2(v10 * QSCALE, v11 * QSCALE);
            } else if (mode == 1) {   // K: fp16
                *(uint32_t*)(outk + (long)r * 512 + c) = pack_h2(v00, v01);
                *(uint32_t*)(outk + (long)(r + 8) * 512 + c) = pack_h2(v10, v11);
            } else if (mode == 2) {   // V: fp16 transposed [b][hk][d][L]
                const int hk = c >> 6, d = c & 63;
                const int bb = r >> 11, lrow = r & 2047;
                const long base = ((long)(bb * NHKV + hk) * HD + d) * LL + lrow;
                outvt[base] = __float2half(v00);
                outvt[base + LL] = __float2half(v01);
                outvt[base + 8] = __float2half(v10);
                outvt[base + LL + 8] = __float2half(v11);
            } else {                  // O: fp32 out
                *(float2*)(outf + (long)r * 2048 + c) = make_float2(v00, v01);
                *(float2*)(outf + (long)(r + 8) * 2048 + c) = make_float2(v10, v11);
            }
        }
    }
}

// ---------------------------------------------------------------------------
// fp16 tensor-core flash attention (exp2 softmax, register P, l via ones-MMA).
// Block: 128 q rows x head x batch. 256 threads (8 warps), warp = 16 q rows.
// V smem has 72 d-rows: rows 0-63 = V, row 64 = ones (row-sum trick), 65-71 = 0.
// ---------------------------------------------------------------------------
#define ASTR 36                         // words per row (32 data + 4 pad)
#define KT_W  (64 * ASTR)               // 2304 words per K buffer
#define KT_WV (72 * ASTR)               // 2592 words per V buffer
#define ATT_SMEM ((2 * KT_W + 2 * KT_WV) * 4)   // 39168 B
#define NKT (LL / 64)

__global__ __launch_bounds__(256, 2) void attn_f16(
    const __half* __restrict__ q, const __half* __restrict__ k,
    const __half* __restrict__ vt, __half* __restrict__ ctx)
{
    extern __shared__ uint32_t smw[];
    uint32_t* KsW = smw;                 // 2 x [64][36]
    uint32_t* VsW = smw + 2 * KT_W;      // 2 x [72][36]
    const uint32_t ks_s = (uint32_t)__cvta_generic_to_shared(KsW);
    const uint32_t vs_s = (uint32_t)__cvta_generic_to_shared(VsW);

    const int tid = threadIdx.x;
    const int warp = tid >> 5;
    const int lane = tid & 31;
    const int gid = lane >> 2;
    const int tig = lane & 3;
    const int r8 = lane & 7;
    const int qd = lane >> 3;
    const int qt = blockIdx.x;
    const int h  = blockIdx.y;
    const int b  = blockIdx.z;
    const int hk = h >> 2;
    const int qbase = qt * 128;

    const int bt_row = (qd >> 1) * 8 + r8;
    const int bt_col = (qd & 1) * 4;
    // ones-tile ldmatrix.x2 address components (lanes 0-15 meaningful)
    const int o_row = 64 + r8;
    const int o_col = ((lane >> 3) & 1) * 4;

    // static V rows 64-71: row 64 = 1.0h pairs, rows 65-71 = 0 (both buffers)
    for (int idx = tid; idx < 2 * 8 * ASTR; idx += 256) {
        const int bufi = idx / (8 * ASTR);
        const int rem = idx % (8 * ASTR);
        const int row = 64 + rem / ASTR;
        const int wcol = rem % ASTR;
        VsW[bufi * KT_WV + row * ASTR + wcol] = (row == 64) ? 0x3C003C00u : 0u;
    }

    // Q fragments (fp16, pre-scaled by log2e/8). 4 k16-steps over HD=64.
    uint32_t qf[4][4];
    {
        const __half* qp = q + (long)(b * LL + qbase + warp * 16 + gid) * (NHQ * HD) + h * HD;
        const __half* qp8 = qp + (long)8 * (NHQ * HD);
#pragma unroll
        for (int ks = 0; ks < 4; ks++) {
            const int c = ks * 16 + 2 * tig;
            qf[ks][0] = *(const uint32_t*)(qp + c);
            qf[ks][1] = *(const uint32_t*)(qp8 + c);
            qf[ks][2] = *(const uint32_t*)(qp + c + 8);
            qf[ks][3] = *(const uint32_t*)(qp8 + c + 8);
        }
    }

    float o[8][4];
    float o8[4];                 // row-sum accumulator (l) via ones column
    float m[2];
#pragma unroll
    for (int nt = 0; nt < 8; nt++)
#pragma unroll
        for (int r = 0; r < 4; r++) o[nt][r] = 0.0f;
#pragma unroll
    for (int r = 0; r < 4; r++) o8[r] = 0.0f;
    m[0] = m[1] = -1e30f;

    const __half* kbase = k + (long)(b * LL) * (NHKV * HD) + hk * HD;
    const __half* vbase = vt + (long)(b * NHKV + hk) * HD * LL;

    auto load_kv = [&](int buf, int kt) {
#pragma unroll
        for (int j = 0; j < 2; j++) {
            const int c = tid + 256 * j;
            const int row = c >> 3;
            const int cc = c & 7;
            cpasync16(ks_s + ((buf * KT_W) + row * ASTR + cc * 4) * 4,
                      kbase + (long)(kt * 64 + row) * (NHKV * HD) + cc * 8);
            cpasync16(vs_s + ((buf * KT_WV) + row * ASTR + cc * 4) * 4,
                      vbase + (long)row * LL + kt * 64 + cc * 8);
        }
        cp_commit();
    };

    load_kv(0, 0);

#pragma unroll 1
    for (int kt = 0; kt < NKT; kt++) {
        const int buf = kt & 1;
        cp_wait<0>();
        __syncthreads();
        if (kt + 1 < NKT) load_kv(buf ^ 1, kt + 1);

        const uint32_t kb = ks_s + (uint32_t)(buf * KT_W) * 4u;
        const uint32_t vb = vs_s + (uint32_t)(buf * KT_WV) * 4u;

        // ---- S = Q @ K^T (log2 domain) ----
        float sacc[8][4];
#pragma unroll
        for (int nt = 0; nt < 8; nt++)
#pragma unroll
            for (int r = 0; r < 4; r++) sacc[nt][r] = 0.0f;

#pragma unroll
        for (int ks = 0; ks < 4; ks++) {
            uint32_t bf[8][2];
#pragma unroll
            for (int p = 0; p < 8; p += 2)
                ldsm_x4(bf[p][0], bf[p][1], bf[p + 1][0], bf[p + 1][1],
                        kb + ((p * 8 + bt_row) * ASTR + ks * 8 + bt_col) * 4);
#pragma unroll
            for (int nt = 0; nt < 8; nt++)
                mma_f16(sacc[nt], qf[ks], bf[nt]);
        }

        // ---- online softmax (exp2); P into A-frag registers; no rs sums ----
        uint32_t ph[8][2];
#pragma unroll
        for (int i = 0; i < 2; i++) {
            const int r0 = 2 * i;
            float tm = -1e30f;
#pragma unroll
            for (int nt = 0; nt < 8; nt++)
                tm = fmaxf(tm, fmaxf(sacc[nt][r0], sacc[nt][r0 + 1]));
            tm = fmaxf(tm, __shfl_xor_sync(0xffffffffu, tm, 1));
            tm = fmaxf(tm, __shfl_xor_sync(0xffffffffu, tm, 2));
            const float mn = fmaxf(m[i], tm);
            const float alpha = ex2f(m[i] - mn);
            m[i] = mn;
#pragma unroll
            for (int nt = 0; nt < 8; nt++) {
                float p0 = ex2f(sacc[nt][r0] - mn);
                float p1 = ex2f(sacc[nt][r0 + 1] - mn);
                ph[nt][i] = pack_h2(p0, p1);
            }
#pragma unroll
            for (int nt = 0; nt < 8; nt++) {
                o[nt][r0]     *= alpha;
                o[nt][r0 + 1] *= alpha;
            }
            o8[r0]     *= alpha;
            o8[r0 + 1] *= alpha;
        }

        // ---- O += P @ V (P register-resident; +ones column for l) ----
#pragma unroll
        for (int ks = 0; ks < 4; ks++) {
            uint32_t vf[8][2];
            uint32_t pf[4] = { ph[2 * ks][0], ph[2 * ks][1],
                               ph[2 * ks + 1][0], ph[2 * ks + 1][1] };
#pragma unroll
            for (int p = 0; p < 8; p += 2)
                ldsm_x4(vf[p][0], vf[p][1], vf[p + 1][0], vf[p + 1][1],
                        vb + ((p * 8 + bt_row) * ASTR + ks * 8 + bt_col) * 4);
#pragma unroll
            for (int nt = 0; nt < 8; nt++)
                mma_f16(o[nt], pf, vf[nt]);
            uint32_t v8[2];
            ldsm_x2(v8[0], v8[1], vb + (o_row * ASTR + ks * 8 + o_col) * 4);
            mma_f16(o8, pf, v8);
        }
    }

    // ---- recover l (col 64 lives at tig==0), normalize + fp16 store ----
    {
        const int src = lane & ~3;
        const float l0 = __shfl_sync(0xffffffffu, o8[0], src);
        const float l1 = __shfl_sync(0xffffffffu, o8[2], src);
        const float inv0 = 1.0f / l0;
        const float inv1 = 1.0f / l1;
        __half* cp0 = ctx + (long)(b * LL + qbase + warp * 16 + gid) * (NHQ * HD) + h * HD;
        __half* cp1 = cp0 + (long)8 * (NHQ * HD);
#pragma unroll
        for (int nt = 0; nt < 8; nt++) {
            const int c0 = nt * 8 + 2 * tig;
            *(uint32_t*)(cp0 + c0) = pack_h2(o[nt][0] * inv0, o[nt][1] * inv0);
            *(uint32_t*)(cp1 + c0) = pack_h2(o[nt][2] * inv1, o[nt][3] * inv1);
        }
    }
}

// ---------------------------------------------------------------------------
extern "C" void kernel_launch(void* const* d_in, const int* in_sizes, int n_in,
                              void* d_out, int out_size)
{
    const float* x  = (const float*)d_in[0];
    const float* Wq = (const float*)d_in[1];
    const float* bq = (const float*)d_in[2];
    const float* Wk = (const float*)d_in[3];
    const float* bk = (const float*)d_in[4];
    const float* Wv = (const float*)d_in[5];
    const float* bv = (const float*)d_in[6];
    const float* Wo = (const float*)d_in[7];
    const float* bo = (const float*)d_in[8];
    float* out = (float*)d_out;

    __half *gxh, *gwqt, *gwkt, *gwvt, *gwot, *gq, *gk, *gvt, *gctx;
    cudaGetSymbolAddress((void**)&gxh, g_xh);
    cudaGetSymbolAddress((void**)&gwqt, g_wqt);
    cudaGetSymbolAddress((void**)&gwkt, g_wkt);
    cudaGetSymbolAddress((void**)&gwvt, g_wvt);
    cudaGetSymbolAddress((void**)&gwot, g_wot);
    cudaGetSymbolAddress((void**)&gq, g_q);
    cudaGetSymbolAddress((void**)&gk, g_k);
    cudaGetSymbolAddress((void**)&gvt, g_vt);
    cudaGetSymbolAddress((void**)&gctx, g_ctx);

    const int M = BB * LL;   // 4096

    cudaFuncSetAttribute(gemm_f16, cudaFuncAttributeMaxDynamicSharedMemorySize, GSMEM);
    cudaFuncSetAttribute(attn_f16, cudaFuncAttributeMaxDynamicSharedMemorySize, ATT_SMEM);

    // prep needed for QKV (Wo transpose deferred past attention)
    {
        const int nx = M * DD;
        cvt_h_kernel<<<nx / 1024, 256>>>(x, gxh, nx);
        dim3 blk(32, 8);
        transpose_h_kernel<<<dim3((NHQ * HD) / 32, DD / 32), blk>>>(Wq, gwqt, DD, NHQ * HD);
        transpose_h_kernel<<<dim3((NHKV * HD) / 32, DD / 32), blk>>>(Wk, gwkt, DD, NHKV * HD);
        transpose_h_kernel<<<dim3((NHKV * HD) / 32, DD / 32), blk>>>(Wv, gwvt, DD, NHKV * HD);
    }

    // fused QKV projections
    gemm_f16<<<768, 256, GSMEM>>>(gxh, gwqt, gwkt, gwvt, bq, bk, bv,
                                  gq, gk, gvt, out, 1);

    // attention
    {
        dim3 grid(LL / 128, NHQ, BB);
        attn_f16<<<grid, 256, ATT_SMEM>>>(gq, gk, gvt, gctx);
    }

    // Wo transpose (only needed by O projection)
    {
        dim3 blk(32, 8);
        transpose_h_kernel<<<dim3(DD / 32, (NHQ * HD) / 32), blk>>>(Wo, gwot, NHQ * HD, DD);
    }

    // O projection (fp32 out)
    gemm_f16<<<512, 256, GSMEM>>>(gctx, gwot, gwot, gwot, bo, bo, bo,
                                  gq, gk, gvt, out, 0);
}